// round 10
// baseline (speedup 1.0000x reference)
#include <cuda_runtime.h>
#include <math.h>
#include <stdint.h>

// Problem dims (fixed by the reference)
#define BDIM 64
#define TDIM 512
#define HDIM 1024
#define KQ   49
#define MT_ROWS (BDIM*TDIM)   // 32768

// ---------------- static scratch (no allocs allowed) ----------------
__device__ float g_st[33554432];        // s_t  [B*T, H]   (128 MB)
__device__ float g_g [MT_ROWS * 64];    // g    [B*T, 49] padded to 64
__device__ float g_cs[MT_ROWS * 64];    // content_s raw (s_t@Ws^T)
__device__ float g_cv[3200 * 64];       // cv   [B*49, 49] padded rows/cols
__device__ float g_al[MT_ROWS * 64];    // alpha [B*T, 49] padded
__device__ float g_be[MT_ROWS];         // beta  [B*T]

// ---------------- tf32 helpers ----------------
__device__ __forceinline__ unsigned f2tf32(float x){
    unsigned u; asm("cvt.rna.tf32.f32 %0, %1;" : "=r"(u) : "f"(x)); return u;
}
__device__ __forceinline__ void mma_tf32(float c[4],
        unsigned a0, unsigned a1, unsigned a2, unsigned a3,
        unsigned b0, unsigned b1){
    asm volatile(
        "mma.sync.aligned.m16n8k8.row.col.f32.tf32.tf32.f32 "
        "{%0,%1,%2,%3}, {%4,%5,%6,%7}, {%8,%9}, {%0,%1,%2,%3};\n"
        : "+f"(c[0]), "+f"(c[1]), "+f"(c[2]), "+f"(c[3])
        : "r"(a0), "r"(a1), "r"(a2), "r"(a3), "r"(b0), "r"(b1));
}

// ---------------- tf32 GEMM: out[m,n] = sum_k A[m,k]*Bm[n,k] ----------------
// Block tile 128x64, BK=16, 8 warps (4x2), warp tile 32x32 (2x4 m16n8 frags).
// EPI==0 : out = sigmoid(acc) * tanh(cells)   (s_t path, exact tiles, ld=HDIM)
// EPI==1 : out[m*ldout+n] = acc, guarded by Mreal/Nreal
template<int EPI>
__global__ void __launch_bounds__(256, 2)
gemm_tf32_kernel(const float* __restrict__ A, const float* __restrict__ Bm,
                 const float* __restrict__ cells, float* __restrict__ out,
                 int Mreal, int Nreal, int ldout)
{
    __shared__ __align__(16) float As[128][20];  // stride 20 -> conflict-free frags
    __shared__ __align__(16) float Bs[64][20];

    const int tid  = threadIdx.x;
    const int lane = tid & 31;
    const int warp = tid >> 5;
    const int grp  = lane >> 2;     // 0..7
    const int qid  = lane & 3;      // 0..3
    const int wm   = warp >> 1;     // 0..3
    const int wn   = warp & 1;      // 0..1

    const int m0 = blockIdx.y * 128;
    const int n0 = blockIdx.x * 64;

    const int lrow = tid >> 2;      // 0..63
    const int lq   = tid & 3;

    float c[2][4][4];
    #pragma unroll
    for (int i = 0; i < 2; i++)
        #pragma unroll
        for (int j = 0; j < 4; j++)
            #pragma unroll
            for (int r = 0; r < 4; r++) c[i][j][r] = 0.f;

    for (int k0 = 0; k0 < HDIM; k0 += 16) {
        // ---- global -> smem (convert to tf32 once) ----
        #pragma unroll
        for (int half = 0; half < 2; half++) {
            int r = lrow + half * 64;
            int m = m0 + r;
            float4 v = make_float4(0.f, 0.f, 0.f, 0.f);
            if (m < Mreal)
                v = *(const float4*)(A + (size_t)m * HDIM + k0 + lq * 4);
            unsigned* dst = (unsigned*)&As[r][lq * 4];
            dst[0] = f2tf32(v.x); dst[1] = f2tf32(v.y);
            dst[2] = f2tf32(v.z); dst[3] = f2tf32(v.w);
        }
        {
            int n = n0 + lrow;
            float4 v = make_float4(0.f, 0.f, 0.f, 0.f);
            if (n < Nreal)
                v = *(const float4*)(Bm + (size_t)n * HDIM + k0 + lq * 4);
            unsigned* dst = (unsigned*)&Bs[lrow][lq * 4];
            dst[0] = f2tf32(v.x); dst[1] = f2tf32(v.y);
            dst[2] = f2tf32(v.z); dst[3] = f2tf32(v.w);
        }
        __syncthreads();

        // ---- two k8 steps ----
        #pragma unroll
        for (int kk = 0; kk < 2; kk++) {
            unsigned a[2][4], b[4][2];
            #pragma unroll
            for (int mt = 0; mt < 2; mt++) {
                int rb = wm * 32 + mt * 16 + grp;
                a[mt][0] = __float_as_uint(As[rb    ][kk * 8 + qid    ]);
                a[mt][1] = __float_as_uint(As[rb + 8][kk * 8 + qid    ]);
                a[mt][2] = __float_as_uint(As[rb    ][kk * 8 + qid + 4]);
                a[mt][3] = __float_as_uint(As[rb + 8][kk * 8 + qid + 4]);
            }
            #pragma unroll
            for (int nt = 0; nt < 4; nt++) {
                int nb = wn * 32 + nt * 8 + grp;
                b[nt][0] = __float_as_uint(Bs[nb][kk * 8 + qid    ]);
                b[nt][1] = __float_as_uint(Bs[nb][kk * 8 + qid + 4]);
            }
            #pragma unroll
            for (int mt = 0; mt < 2; mt++)
                #pragma unroll
                for (int nt = 0; nt < 4; nt++)
                    mma_tf32(c[mt][nt], a[mt][0], a[mt][1], a[mt][2], a[mt][3],
                             b[nt][0], b[nt][1]);
        }
        __syncthreads();
    }

    // ---- epilogue ----
    #pragma unroll
    for (int mt = 0; mt < 2; mt++) {
        #pragma unroll
        for (int nt = 0; nt < 4; nt++) {
            int m = m0 + wm * 32 + mt * 16 + grp;
            int n = n0 + wn * 32 + nt * 8 + qid * 2;
            #pragma unroll
            for (int half = 0; half < 2; half++) {
                int mm = m + half * 8;
                float v0 = c[mt][nt][half * 2 + 0];
                float v1 = c[mt][nt][half * 2 + 1];
                if (EPI == 0) {
                    size_t idx = (size_t)mm * HDIM + n;
                    float2 cl = *(const float2*)(cells + idx);
                    float s0 = 1.f / (1.f + expf(-v0));
                    float s1 = 1.f / (1.f + expf(-v1));
                    float2 o;
                    o.x = s0 * tanhf(cl.x);
                    o.y = s1 * tanhf(cl.y);
                    *(float2*)(out + idx) = o;
                } else {
                    if (mm < Mreal) {
                        size_t row = (size_t)mm * ldout;
                        if (n     < Nreal) out[row + n    ] = v0;
                        if (n + 1 < Nreal) out[row + n + 1] = v1;
                    }
                }
            }
        }
    }
}

// ---------------- attention logits: alpha, beta per (b,t) ----------------
__global__ void __launch_bounds__(64)
attn_logits_kernel(const float* __restrict__ Wh)
{
    const int t  = blockIdx.x;
    const int b  = blockIdx.y;
    const int bt = b * TDIM + t;
    const int tid = threadIdx.x;

    __shared__ float cvsh[KQ * KQ];
    __shared__ float gsh[KQ], cssh[KQ], whsh[64];
    __shared__ float zsh[64], red[64];

    for (int i = tid; i < KQ * KQ; i += 64) {
        int k = i / KQ, j = i - k * KQ;
        cvsh[i] = g_cv[(size_t)(b * KQ + k) * 64 + j];
    }
    if (tid < KQ) {
        gsh[tid]  = g_g [(size_t)bt * 64 + tid];
        cssh[tid] = g_cs[(size_t)bt * 64 + tid];
    }
    whsh[tid] = (tid < KQ) ? Wh[tid] : 0.f;
    __syncthreads();

    // z_ext = sum_j tanh(cs_j + g_j) * Wh_j
    float e = 0.f;
    if (tid < KQ) e = tanhf(cssh[tid] + gsh[tid]) * whsh[tid];
    red[tid] = e;
    __syncthreads();
    for (int s = 32; s > 0; s >>= 1) {
        if (tid < s) red[tid] += red[tid + s];
        __syncthreads();
    }
    float zx = red[0];
    __syncthreads();

    // z_k = sum_j tanh(cv[b,k,j] + g_j) * Wh_j
    float z = -1e30f;
    if (tid < KQ) {
        float acc = 0.f;
        const float* cvr = &cvsh[tid * KQ];
        #pragma unroll 7
        for (int j = 0; j < KQ; j++)
            acc += tanhf(cvr[j] + gsh[j]) * whsh[j];
        z = acc;
    }
    zsh[tid] = z;
    red[tid] = z;
    __syncthreads();
    for (int s = 32; s > 0; s >>= 1) {
        if (tid < s) red[tid] = fmaxf(red[tid], red[tid + s]);
        __syncthreads();
    }
    float mx = red[0];
    __syncthreads();

    float ez = (tid < KQ) ? expf(zsh[tid] - mx) : 0.f;
    red[tid] = ez;
    __syncthreads();
    for (int s = 32; s > 0; s >>= 1) {
        if (tid < s) red[tid] += red[tid + s];
        __syncthreads();
    }
    float sum49 = red[0];

    if (tid < KQ) g_al[(size_t)bt * 64 + tid] = ez / sum49;
    if (tid == 0) {
        float M2 = fmaxf(mx, zx);
        float denom = expf(mx - M2) * sum49 + expf(zx - M2);
        g_be[bt] = expf(zx - M2) / denom;
    }
}

// ---------------- final: out = beta*s_t + (1-beta)*(alpha@V) + hiddens ------
__global__ void __launch_bounds__(256)
final_kernel(const float* __restrict__ V, const float* __restrict__ hiddens,
             float* __restrict__ out)
{
    const int b  = blockIdx.z;
    const int t0 = blockIdx.y * 16;
    const int h0 = blockIdx.x * 256;
    const int tid  = threadIdx.x;
    const int hthr = tid & 63;      // 64 h-groups of 4
    const int tthr = tid >> 6;      // 4 t-groups of 4

    __shared__ float al[16][52];
    __shared__ float be[16];

    for (int i = tid; i < 16 * KQ; i += 256) {
        int tt = i / KQ, k = i - tt * KQ;
        al[tt][k] = g_al[(size_t)(b * TDIM + t0 + tt) * 64 + k];
    }
    if (tid < 16) be[tid] = g_be[b * TDIM + t0 + tid];
    __syncthreads();

    const int h = h0 + hthr * 4;
    float4 acc[4];
    #pragma unroll
    for (int i = 0; i < 4; i++) acc[i] = make_float4(0.f, 0.f, 0.f, 0.f);

    const float* Vb = V + (size_t)b * KQ * HDIM + h;
    for (int k = 0; k < KQ; k++) {
        float4 v = *(const float4*)(Vb + (size_t)k * HDIM);
        #pragma unroll
        for (int i = 0; i < 4; i++) {
            float a = al[tthr * 4 + i][k];
            acc[i].x += a * v.x; acc[i].y += a * v.y;
            acc[i].z += a * v.z; acc[i].w += a * v.w;
        }
    }
    #pragma unroll
    for (int i = 0; i < 4; i++) {
        int t = t0 + tthr * 4 + i;
        size_t idx = ((size_t)(b * TDIM + t)) * HDIM + h;
        float4 s  = *(const float4*)(g_st + idx);
        float4 hd = *(const float4*)(hiddens + idx);
        float bt = be[tthr * 4 + i];
        float om = 1.f - bt;
        float4 o;
        o.x = bt * s.x + om * acc[i].x + hd.x;
        o.y = bt * s.y + om * acc[i].y + hd.y;
        o.z = bt * s.z + om * acc[i].z + hd.z;
        o.w = bt * s.w + om * acc[i].w + hd.w;
        *(float4*)(out + idx) = o;
    }
}

// ---------------- launch ----------------
extern "C" void kernel_launch(void* const* d_in, const int* in_sizes, int n_in,
                              void* d_out, int out_size)
{
    const float* x       = (const float*)d_in[0];
    const float* hiddens = (const float*)d_in[1];
    const float* cells   = (const float*)d_in[2];
    const float* V       = (const float*)d_in[3];
    const float* Wx      = (const float*)d_in[4];
    // d_in[5] = Whh, unused: h_prev == 0 so its contribution is exactly zero.
    const float* Wv      = (const float*)d_in[6];
    const float* Wg      = (const float*)d_in[7];
    const float* Ws      = (const float*)d_in[8];
    const float* Wh      = (const float*)d_in[9];
    float* out = (float*)d_out;

    float *p_st, *p_g, *p_cs, *p_cv;
    cudaGetSymbolAddress((void**)&p_st, g_st);
    cudaGetSymbolAddress((void**)&p_g,  g_g);
    cudaGetSymbolAddress((void**)&p_cs, g_cs);
    cudaGetSymbolAddress((void**)&p_cv, g_cv);

    // s_t = sigmoid(x @ Wx^T) * tanh(cells)       [32768 x 1024]
    gemm_tf32_kernel<0><<<dim3(16, 256), 256>>>(x, Wx, cells, p_st,
                                                MT_ROWS, HDIM, HDIM);
    // g = hiddens @ Wg^T                          [32768 x 49]
    gemm_tf32_kernel<1><<<dim3(1, 256), 256>>>(hiddens, Wg, nullptr, p_g,
                                               MT_ROWS, KQ, 64);
    // cs = s_t @ Ws^T                             [32768 x 49] (after s_t)
    gemm_tf32_kernel<1><<<dim3(1, 256), 256>>>(p_st, Ws, nullptr, p_cs,
                                               MT_ROWS, KQ, 64);
    // cv = V @ Wv^T  (V viewed as [B*49, 1024])   [3136 x 49]
    gemm_tf32_kernel<1><<<dim3(1, 25), 256>>>(V, Wv, nullptr, p_cv,
                                              3136, KQ, 64);
    // alpha / beta per (b,t)
    attn_logits_kernel<<<dim3(TDIM, BDIM), 64>>>(Wh);
    // out = beta*s_t + (1-beta)*(alpha@V) + hiddens
    final_kernel<<<dim3(4, 32, 64), 256>>>(V, hiddens, out);
}

// round 11
// speedup vs baseline: 1.0018x; 1.0018x over previous
#include <cuda_runtime.h>
#include <math.h>
#include <stdint.h>

// Problem dims (fixed by the reference)
#define BDIM 64
#define TDIM 512
#define HDIM 1024
#define KQ   49
#define MT_ROWS (BDIM*TDIM)   // 32768

// ---------------- static scratch (no allocs allowed) ----------------
__device__ float g_st[33554432];        // s_t  [B*T, H]   (128 MB)
__device__ float g_g [MT_ROWS * 64];    // g    [B*T, 49] padded to 64
__device__ float g_cs[MT_ROWS * 64];    // content_s raw (s_t@Ws^T)
__device__ float g_cv[3200 * 64];       // cv   [B*49, 49] padded rows/cols
__device__ float g_al[MT_ROWS * 64];    // alpha [B*T, 49] padded
__device__ float g_be[MT_ROWS];         // beta  [B*T]

// ---------------- tf32 helpers ----------------
__device__ __forceinline__ unsigned f2tf32(float x){
    unsigned u; asm("cvt.rna.tf32.f32 %0, %1;" : "=r"(u) : "f"(x)); return u;
}
__device__ __forceinline__ void mma_tf32(float c[4],
        unsigned a0, unsigned a1, unsigned a2, unsigned a3,
        unsigned b0, unsigned b1){
    asm volatile(
        "mma.sync.aligned.m16n8k8.row.col.f32.tf32.tf32.f32 "
        "{%0,%1,%2,%3}, {%4,%5,%6,%7}, {%8,%9}, {%0,%1,%2,%3};\n"
        : "+f"(c[0]), "+f"(c[1]), "+f"(c[2]), "+f"(c[3])
        : "r"(a0), "r"(a1), "r"(a2), "r"(a3), "r"(b0), "r"(b1));
}

// ---------------- tf32 GEMM: out[m,n] = sum_k A[m,k]*Bm[n,k] ----------------
// Block tile 128x64, BK=16, 8 warps (4x2), warp tile 32x32 (2x4 m16n8 frags).
// EPI==0 : out = sigmoid(acc) * tanh(cells)   (s_t path, exact tiles, ld=HDIM)
// EPI==1 : out[m*ldout+n] = acc, guarded by Mreal/Nreal
template<int EPI>
__global__ void __launch_bounds__(256, 2)
gemm_tf32_kernel(const float* __restrict__ A, const float* __restrict__ Bm,
                 const float* __restrict__ cells, float* __restrict__ out,
                 int Mreal, int Nreal, int ldout)
{
    __shared__ __align__(16) float As[128][20];  // stride 20 -> conflict-free frags
    __shared__ __align__(16) float Bs[64][20];

    const int tid  = threadIdx.x;
    const int lane = tid & 31;
    const int warp = tid >> 5;
    const int grp  = lane >> 2;     // 0..7
    const int qid  = lane & 3;      // 0..3
    const int wm   = warp >> 1;     // 0..3
    const int wn   = warp & 1;      // 0..1

    const int m0 = blockIdx.y * 128;
    const int n0 = blockIdx.x * 64;

    const int lrow = tid >> 2;      // 0..63
    const int lq   = tid & 3;

    float c[2][4][4];
    #pragma unroll
    for (int i = 0; i < 2; i++)
        #pragma unroll
        for (int j = 0; j < 4; j++)
            #pragma unroll
            for (int r = 0; r < 4; r++) c[i][j][r] = 0.f;

    for (int k0 = 0; k0 < HDIM; k0 += 16) {
        // ---- global -> smem (convert to tf32 once) ----
        #pragma unroll
        for (int half = 0; half < 2; half++) {
            int r = lrow + half * 64;
            int m = m0 + r;
            float4 v = make_float4(0.f, 0.f, 0.f, 0.f);
            if (m < Mreal)
                v = *(const float4*)(A + (size_t)m * HDIM + k0 + lq * 4);
            unsigned* dst = (unsigned*)&As[r][lq * 4];
            dst[0] = f2tf32(v.x); dst[1] = f2tf32(v.y);
            dst[2] = f2tf32(v.z); dst[3] = f2tf32(v.w);
        }
        {
            int n = n0 + lrow;
            float4 v = make_float4(0.f, 0.f, 0.f, 0.f);
            if (n < Nreal)
                v = *(const float4*)(Bm + (size_t)n * HDIM + k0 + lq * 4);
            unsigned* dst = (unsigned*)&Bs[lrow][lq * 4];
            dst[0] = f2tf32(v.x); dst[1] = f2tf32(v.y);
            dst[2] = f2tf32(v.z); dst[3] = f2tf32(v.w);
        }
        __syncthreads();

        // ---- two k8 steps ----
        #pragma unroll
        for (int kk = 0; kk < 2; kk++) {
            unsigned a[2][4], b[4][2];
            #pragma unroll
            for (int mt = 0; mt < 2; mt++) {
                int rb = wm * 32 + mt * 16 + grp;
                a[mt][0] = __float_as_uint(As[rb    ][kk * 8 + qid    ]);
                a[mt][1] = __float_as_uint(As[rb + 8][kk * 8 + qid    ]);
                a[mt][2] = __float_as_uint(As[rb    ][kk * 8 + qid + 4]);
                a[mt][3] = __float_as_uint(As[rb + 8][kk * 8 + qid + 4]);
            }
            #pragma unroll
            for (int nt = 0; nt < 4; nt++) {
                int nb = wn * 32 + nt * 8 + grp;
                b[nt][0] = __float_as_uint(Bs[nb][kk * 8 + qid    ]);
                b[nt][1] = __float_as_uint(Bs[nb][kk * 8 + qid + 4]);
            }
            #pragma unroll
            for (int mt = 0; mt < 2; mt++)
                #pragma unroll
                for (int nt = 0; nt < 4; nt++)
                    mma_tf32(c[mt][nt], a[mt][0], a[mt][1], a[mt][2], a[mt][3],
                             b[nt][0], b[nt][1]);
        }
        __syncthreads();
    }

    // ---- epilogue ----
    #pragma unroll
    for (int mt = 0; mt < 2; mt++) {
        #pragma unroll
        for (int nt = 0; nt < 4; nt++) {
            int m = m0 + wm * 32 + mt * 16 + grp;
            int n = n0 + wn * 32 + nt * 8 + qid * 2;
            #pragma unroll
            for (int half = 0; half < 2; half++) {
                int mm = m + half * 8;
                float v0 = c[mt][nt][half * 2 + 0];
                float v1 = c[mt][nt][half * 2 + 1];
                if (EPI == 0) {
                    size_t idx = (size_t)mm * HDIM + n;
                    float2 cl = *(const float2*)(cells + idx);
                    float s0 = 1.f / (1.f + expf(-v0));
                    float s1 = 1.f / (1.f + expf(-v1));
                    float2 o;
                    o.x = s0 * tanhf(cl.x);
                    o.y = s1 * tanhf(cl.y);
                    *(float2*)(out + idx) = o;
                } else {
                    if (mm < Mreal) {
                        size_t row = (size_t)mm * ldout;
                        if (n     < Nreal) out[row + n    ] = v0;
                        if (n + 1 < Nreal) out[row + n + 1] = v1;
                    }
                }
            }
        }
    }
}

// ---------------- attention logits: alpha, beta per (b,t) ----------------
__global__ void __launch_bounds__(64)
attn_logits_kernel(const float* __restrict__ Wh)
{
    const int t  = blockIdx.x;
    const int b  = blockIdx.y;
    const int bt = b * TDIM + t;
    const int tid = threadIdx.x;

    __shared__ float cvsh[KQ * KQ];
    __shared__ float gsh[KQ], cssh[KQ], whsh[64];
    __shared__ float zsh[64], red[64];

    for (int i = tid; i < KQ * KQ; i += 64) {
        int k = i / KQ, j = i - k * KQ;
        cvsh[i] = g_cv[(size_t)(b * KQ + k) * 64 + j];
    }
    if (tid < KQ) {
        gsh[tid]  = g_g [(size_t)bt * 64 + tid];
        cssh[tid] = g_cs[(size_t)bt * 64 + tid];
    }
    whsh[tid] = (tid < KQ) ? Wh[tid] : 0.f;
    __syncthreads();

    // z_ext = sum_j tanh(cs_j + g_j) * Wh_j
    float e = 0.f;
    if (tid < KQ) e = tanhf(cssh[tid] + gsh[tid]) * whsh[tid];
    red[tid] = e;
    __syncthreads();
    for (int s = 32; s > 0; s >>= 1) {
        if (tid < s) red[tid] += red[tid + s];
        __syncthreads();
    }
    float zx = red[0];
    __syncthreads();

    // z_k = sum_j tanh(cv[b,k,j] + g_j) * Wh_j
    float z = -1e30f;
    if (tid < KQ) {
        float acc = 0.f;
        const float* cvr = &cvsh[tid * KQ];
        #pragma unroll 7
        for (int j = 0; j < KQ; j++)
            acc += tanhf(cvr[j] + gsh[j]) * whsh[j];
        z = acc;
    }
    zsh[tid] = z;
    red[tid] = z;
    __syncthreads();
    for (int s = 32; s > 0; s >>= 1) {
        if (tid < s) red[tid] = fmaxf(red[tid], red[tid + s]);
        __syncthreads();
    }
    float mx = red[0];
    __syncthreads();

    float ez = (tid < KQ) ? expf(zsh[tid] - mx) : 0.f;
    red[tid] = ez;
    __syncthreads();
    for (int s = 32; s > 0; s >>= 1) {
        if (tid < s) red[tid] += red[tid + s];
        __syncthreads();
    }
    float sum49 = red[0];

    if (tid < KQ) g_al[(size_t)bt * 64 + tid] = ez / sum49;
    if (tid == 0) {
        float M2 = fmaxf(mx, zx);
        float denom = expf(mx - M2) * sum49 + expf(zx - M2);
        g_be[bt] = expf(zx - M2) / denom;
    }
}

// ---------------- final: out = beta*s_t + (1-beta)*(alpha@V) + hiddens ------
__global__ void __launch_bounds__(256)
final_kernel(const float* __restrict__ V, const float* __restrict__ hiddens,
             float* __restrict__ out)
{
    const int b  = blockIdx.z;
    const int t0 = blockIdx.y * 16;
    const int h0 = blockIdx.x * 256;
    const int tid  = threadIdx.x;
    const int hthr = tid & 63;      // 64 h-groups of 4
    const int tthr = tid >> 6;      // 4 t-groups of 4

    __shared__ float al[16][52];
    __shared__ float be[16];

    for (int i = tid; i < 16 * KQ; i += 256) {
        int tt = i / KQ, k = i - tt * KQ;
        al[tt][k] = g_al[(size_t)(b * TDIM + t0 + tt) * 64 + k];
    }
    if (tid < 16) be[tid] = g_be[b * TDIM + t0 + tid];
    __syncthreads();

    const int h = h0 + hthr * 4;
    float4 acc[4];
    #pragma unroll
    for (int i = 0; i < 4; i++) acc[i] = make_float4(0.f, 0.f, 0.f, 0.f);

    const float* Vb = V + (size_t)b * KQ * HDIM + h;
    for (int k = 0; k < KQ; k++) {
        float4 v = *(const float4*)(Vb + (size_t)k * HDIM);
        #pragma unroll
        for (int i = 0; i < 4; i++) {
            float a = al[tthr * 4 + i][k];
            acc[i].x += a * v.x; acc[i].y += a * v.y;
            acc[i].z += a * v.z; acc[i].w += a * v.w;
        }
    }
    #pragma unroll
    for (int i = 0; i < 4; i++) {
        int t = t0 + tthr * 4 + i;
        size_t idx = ((size_t)(b * TDIM + t)) * HDIM + h;
        float4 s  = *(const float4*)(g_st + idx);
        float4 hd = *(const float4*)(hiddens + idx);
        float bt = be[tthr * 4 + i];
        float om = 1.f - bt;
        float4 o;
        o.x = bt * s.x + om * acc[i].x + hd.x;
        o.y = bt * s.y + om * acc[i].y + hd.y;
        o.z = bt * s.z + om * acc[i].z + hd.z;
        o.w = bt * s.w + om * acc[i].w + hd.w;
        *(float4*)(out + idx) = o;
    }
}

// ---------------- launch ----------------
extern "C" void kernel_launch(void* const* d_in, const int* in_sizes, int n_in,
                              void* d_out, int out_size)
{
    const float* x       = (const float*)d_in[0];
    const float* hiddens = (const float*)d_in[1];
    const float* cells   = (const float*)d_in[2];
    const float* V       = (const float*)d_in[3];
    const float* Wx      = (const float*)d_in[4];
    // d_in[5] = Whh, unused: h_prev == 0 so its contribution is exactly zero.
    const float* Wv      = (const float*)d_in[6];
    const float* Wg      = (const float*)d_in[7];
    const float* Ws      = (const float*)d_in[8];
    const float* Wh      = (const float*)d_in[9];
    float* out = (float*)d_out;

    float *p_st, *p_g, *p_cs, *p_cv;
    cudaGetSymbolAddress((void**)&p_st, g_st);
    cudaGetSymbolAddress((void**)&p_g,  g_g);
    cudaGetSymbolAddress((void**)&p_cs, g_cs);
    cudaGetSymbolAddress((void**)&p_cv, g_cv);

    // s_t = sigmoid(x @ Wx^T) * tanh(cells)       [32768 x 1024]
    gemm_tf32_kernel<0><<<dim3(16, 256), 256>>>(x, Wx, cells, p_st,
                                                MT_ROWS, HDIM, HDIM);
    // g = hiddens @ Wg^T                          [32768 x 49]
    gemm_tf32_kernel<1><<<dim3(1, 256), 256>>>(hiddens, Wg, nullptr, p_g,
                                               MT_ROWS, KQ, 64);
    // cs = s_t @ Ws^T                             [32768 x 49] (after s_t)
    gemm_tf32_kernel<1><<<dim3(1, 256), 256>>>(p_st, Ws, nullptr, p_cs,
                                               MT_ROWS, KQ, 64);
    // cv = V @ Wv^T  (V viewed as [B*49, 1024])   [3136 x 49]
    gemm_tf32_kernel<1><<<dim3(1, 25), 256>>>(V, Wv, nullptr, p_cv,
                                              3136, KQ, 64);
    // alpha / beta per (b,t)
    attn_logits_kernel<<<dim3(TDIM, BDIM), 64>>>(Wh);
    // out = beta*s_t + (1-beta)*(alpha@V) + hiddens
    final_kernel<<<dim3(4, 32, 64), 256>>>(V, hiddens, out);
}

// round 14
// speedup vs baseline: 1.7600x; 1.7569x over previous
#include <cuda_runtime.h>
#include <cuda_fp16.h>
#include <cuda_bf16.h>
#include <math.h>
#include <stdint.h>

// Problem dims (fixed by the reference)
#define BDIM 64
#define TDIM 512
#define HDIM 1024
#define KQ   49
#define MT_ROWS (BDIM*TDIM)   // 32768

// ---------------- static scratch (no allocs allowed) ----------------
__device__ __half g_st[33554432];              // s_t  [B*T, H] fp16 (64 MB)
__device__ __nv_bfloat16 g_xb[33554432];       // x in bf16      (64 MB)
__device__ __nv_bfloat16 g_wb[HDIM * HDIM];    // Wx in bf16     (2 MB)
__device__ float g_g [MT_ROWS * 64];           // g   [B*T, 49] padded to 64
__device__ float g_cs[MT_ROWS * 64];           // content_s raw (s_t@Ws^T)
__device__ float g_cv[4 * 3200 * 64];          // cv partials (4 K-slices)
__device__ float g_al[MT_ROWS * 64];           // alpha [B*T, 49] padded
__device__ float g_be[MT_ROWS];                // beta  [B*T]

#define CV_SLICE (3200 * 64)

// ---------------- fast math helpers ----------------
__device__ __forceinline__ float tanh_fast(float x){
    float y; asm("tanh.approx.f32 %0, %1;" : "=f"(y) : "f"(x)); return y;
}
__device__ __forceinline__ unsigned pack_f16(float lo, float hi){
    unsigned r; asm("cvt.rn.f16x2.f32 %0, %1, %2;" : "=r"(r) : "f"(hi), "f"(lo)); return r;
}
__device__ __forceinline__ unsigned pack_bf16(float lo, float hi){
    unsigned r; asm("cvt.rn.bf16x2.f32 %0, %1, %2;" : "=r"(r) : "f"(hi), "f"(lo)); return r;
}

// ---------------- fp32 -> bf16 conversion pass ----------------
__global__ void __launch_bounds__(256)
cvt_bf16_kernel(const float* __restrict__ src, __nv_bfloat16* __restrict__ dst,
                int n4)
{
    int i = blockIdx.x * 256 + threadIdx.x;
    if (i < n4) {
        float4 v = ((const float4*)src)[i];
        uint2 p;
        p.x = pack_bf16(v.x, v.y);
        p.y = pack_bf16(v.z, v.w);
        ((uint2*)dst)[i] = p;
    }
}

// ================= GEMM1: bf16 mma.sync m16n8k16 =================
// s_t = sigmoid(x @ Wx^T) * tanh(cells), stored fp16.
// Tiles: BM=128, BN=128, BK=32 bf16. 8 warps (2m x 4n), warp tile 64x32.
// Double-buffered smem (stride 20 words -> conflict-free fragment LDS),
// register-staged global prefetch, one __syncthreads per K-iter.
#define G1_ROWW 20                 // words per smem row (32 bf16 = 16 words + pad)
#define G1_BUFW (128 * G1_ROWW)    // 2560 words per matrix per buffer

__device__ __forceinline__ void mma_bf16(float c[4], const unsigned a[4],
                                         const unsigned b[2]){
    asm volatile(
        "mma.sync.aligned.m16n8k16.row.col.f32.bf16.bf16.f32 "
        "{%0,%1,%2,%3}, {%4,%5,%6,%7}, {%8,%9}, {%0,%1,%2,%3};\n"
        : "+f"(c[0]), "+f"(c[1]), "+f"(c[2]), "+f"(c[3])
        : "r"(a[0]), "r"(a[1]), "r"(a[2]), "r"(a[3]), "r"(b[0]), "r"(b[1]));
}

__global__ void __launch_bounds__(256, 2)
gemm1_bf16_kernel(const float* __restrict__ cells)
{
    __shared__ __align__(16) unsigned As[2][G1_BUFW];
    __shared__ __align__(16) unsigned Bs[2][G1_BUFW];

    const int tid  = threadIdx.x;
    const int lane = tid & 31;
    const int warp = tid >> 5;
    const int grp  = lane >> 2;     // 0..7
    const int qid  = lane & 3;      // 0..3
    const int wm   = warp >> 2;     // 0..1
    const int wn   = warp & 3;      // 0..3

    const int m0 = blockIdx.y * 128;
    const int n0 = blockIdx.x * 128;

    // load chunk mapping: 512 uint4 chunks (128 rows x 4 chunks of 8 bf16), 2/thr
    const int r0 = tid >> 2,         cg0 = tid & 3;
    const int r1 = (tid + 256) >> 2, cg1 = (tid + 256) & 3;

    const __nv_bfloat16* __restrict__ xb = g_xb;
    const __nv_bfloat16* __restrict__ wb = g_wb;

    float c[4][4][4];
    #pragma unroll
    for (int i = 0; i < 4; i++)
        #pragma unroll
        for (int j = 0; j < 4; j++)
            #pragma unroll
            for (int r = 0; r < 4; r++) c[i][j][r] = 0.f;

    // ---- prologue: load tile 0 ---- (chunk = 8 bf16 elements = one uint4)
    {
        uint4 a0 = *(const uint4*)(xb + (size_t)(m0 + r0) * HDIM + cg0 * 8);
        uint4 a1 = *(const uint4*)(xb + (size_t)(m0 + r1) * HDIM + cg1 * 8);
        uint4 b0 = *(const uint4*)(wb + (size_t)(n0 + r0) * HDIM + cg0 * 8);
        uint4 b1 = *(const uint4*)(wb + (size_t)(n0 + r1) * HDIM + cg1 * 8);
        *(uint4*)(&As[0][r0 * G1_ROWW + cg0 * 4]) = a0;
        *(uint4*)(&As[0][r1 * G1_ROWW + cg1 * 4]) = a1;
        *(uint4*)(&Bs[0][r0 * G1_ROWW + cg0 * 4]) = b0;
        *(uint4*)(&Bs[0][r1 * G1_ROWW + cg1 * 4]) = b1;
    }
    __syncthreads();

    for (int kt = 0; kt < 32; kt++) {
        const unsigned* Ac = As[kt & 1];
        const unsigned* Bc = Bs[kt & 1];

        uint4 a0, a1, b0, b1;
        if (kt < 31) {
            const int k0 = (kt + 1) * 32;
            a0 = *(const uint4*)(xb + (size_t)(m0 + r0) * HDIM + k0 + cg0 * 8);
            a1 = *(const uint4*)(xb + (size_t)(m0 + r1) * HDIM + k0 + cg1 * 8);
            b0 = *(const uint4*)(wb + (size_t)(n0 + r0) * HDIM + k0 + cg0 * 8);
            b1 = *(const uint4*)(wb + (size_t)(n0 + r1) * HDIM + k0 + cg1 * 8);
        }

        #pragma unroll
        for (int kk = 0; kk < 2; kk++) {
            unsigned af[4][4], bf[4][2];
            #pragma unroll
            for (int mt = 0; mt < 4; mt++) {
                const int rb = wm * 64 + mt * 16 + grp;
                af[mt][0] = Ac[ rb      * G1_ROWW + kk * 8 + qid    ];
                af[mt][1] = Ac[(rb + 8) * G1_ROWW + kk * 8 + qid    ];
                af[mt][2] = Ac[ rb      * G1_ROWW + kk * 8 + qid + 4];
                af[mt][3] = Ac[(rb + 8) * G1_ROWW + kk * 8 + qid + 4];
            }
            #pragma unroll
            for (int nt = 0; nt < 4; nt++) {
                const int nb = wn * 32 + nt * 8 + grp;
                bf[nt][0] = Bc[nb * G1_ROWW + kk * 8 + qid    ];
                bf[nt][1] = Bc[nb * G1_ROWW + kk * 8 + qid + 4];
            }
            #pragma unroll
            for (int mt = 0; mt < 4; mt++)
                #pragma unroll
                for (int nt = 0; nt < 4; nt++)
                    mma_bf16(c[mt][nt], af[mt], bf[nt]);
        }

        if (kt < 31) {
            unsigned* An = As[(kt + 1) & 1];
            unsigned* Bn = Bs[(kt + 1) & 1];
            *(uint4*)(&An[r0 * G1_ROWW + cg0 * 4]) = a0;
            *(uint4*)(&An[r1 * G1_ROWW + cg1 * 4]) = a1;
            *(uint4*)(&Bn[r0 * G1_ROWW + cg0 * 4]) = b0;
            *(uint4*)(&Bn[r1 * G1_ROWW + cg1 * 4]) = b1;
        }
        __syncthreads();
    }

    // ---- epilogue: sigmoid(y)*tanh(cells) -> fp16 s_t ----
    #pragma unroll
    for (int mt = 0; mt < 4; mt++) {
        #pragma unroll
        for (int nt = 0; nt < 4; nt++) {
            const int m = m0 + wm * 64 + mt * 16 + grp;
            const int n = n0 + wn * 32 + nt * 8 + qid * 2;
            #pragma unroll
            for (int half = 0; half < 2; half++) {
                const int mm = m + half * 8;
                const float y0 = c[mt][nt][half * 2 + 0];
                const float y1 = c[mt][nt][half * 2 + 1];
                const size_t idx = (size_t)mm * HDIM + n;
                const float2 cl = *(const float2*)(cells + idx);
                const float gate0 = 0.5f + 0.5f * tanh_fast(0.5f * y0);
                const float gate1 = 0.5f + 0.5f * tanh_fast(0.5f * y1);
                const float s0 = gate0 * tanh_fast(cl.x);
                const float s1 = gate1 * tanh_fast(cl.y);
                *(unsigned*)(&g_st[idx]) = pack_f16(s0, s1);
            }
        }
    }
}

// ================= thin tf32 GEMM (g / cs / cv) =================
__device__ __forceinline__ unsigned f2tf32(float x){
    unsigned u; asm("cvt.rna.tf32.f32 %0, %1;" : "=r"(u) : "f"(x)); return u;
}
__device__ __forceinline__ void mma_tf32(float c[4],
        unsigned a0, unsigned a1, unsigned a2, unsigned a3,
        unsigned b0, unsigned b1){
    asm volatile(
        "mma.sync.aligned.m16n8k8.row.col.f32.tf32.tf32.f32 "
        "{%0,%1,%2,%3}, {%4,%5,%6,%7}, {%8,%9}, {%0,%1,%2,%3};\n"
        : "+f"(c[0]), "+f"(c[1]), "+f"(c[2]), "+f"(c[3])
        : "r"(a0), "r"(a1), "r"(a2), "r"(a3), "r"(b0), "r"(b1));
}

// out[m,n] = sum_{k in slice} A[m,k]*Bm[n,k]; AHALF: A is fp16.
// K-split over gridDim.z; slice z writes to out + z*pstride.
template<bool AHALF>
__global__ void __launch_bounds__(256, 2)
gemm_thin_kernel(const void* __restrict__ Ain, const float* __restrict__ Bm,
                 float* __restrict__ out, int Mreal, int Nreal, int ldout,
                 long long pstride)
{
    __shared__ __align__(16) float As[128][20];
    __shared__ __align__(16) float Bs[64][20];

    const int kper = HDIM / gridDim.z;
    const int kb = blockIdx.z * kper;
    const int ke = kb + kper;
    out += (long long)blockIdx.z * pstride;

    const int tid  = threadIdx.x;
    const int lane = tid & 31;
    const int warp = tid >> 5;
    const int grp  = lane >> 2;
    const int qid  = lane & 3;
    const int wm   = warp >> 1;
    const int wn   = warp & 1;
    const int m0 = blockIdx.y * 128;
    const int n0 = blockIdx.x * 64;
    const int lrow = tid >> 2;
    const int lq   = tid & 3;

    float c[2][4][4];
    #pragma unroll
    for (int i = 0; i < 2; i++)
        #pragma unroll
        for (int j = 0; j < 4; j++)
            #pragma unroll
            for (int r = 0; r < 4; r++) c[i][j][r] = 0.f;

    for (int k0 = kb; k0 < ke; k0 += 16) {
        #pragma unroll
        for (int halfm = 0; halfm < 2; halfm++) {
            int r = lrow + halfm * 64;
            int m = m0 + r;
            float4 v = make_float4(0.f, 0.f, 0.f, 0.f);
            if (m < Mreal) {
                if (AHALF) {
                    const __half* A = (const __half*)Ain;
                    uint2 u = *(const uint2*)(A + (size_t)m * HDIM + k0 + lq * 4);
                    float2 f0 = __half22float2(*(__half2*)&u.x);
                    float2 f1 = __half22float2(*(__half2*)&u.y);
                    v = make_float4(f0.x, f0.y, f1.x, f1.y);
                } else {
                    const float* A = (const float*)Ain;
                    v = *(const float4*)(A + (size_t)m * HDIM + k0 + lq * 4);
                }
            }
            unsigned* dst = (unsigned*)&As[r][lq * 4];
            dst[0] = f2tf32(v.x); dst[1] = f2tf32(v.y);
            dst[2] = f2tf32(v.z); dst[3] = f2tf32(v.w);
        }
        {
            int n = n0 + lrow;
            float4 v = make_float4(0.f, 0.f, 0.f, 0.f);
            if (n < Nreal)
                v = *(const float4*)(Bm + (size_t)n * HDIM + k0 + lq * 4);
            unsigned* dst = (unsigned*)&Bs[lrow][lq * 4];
            dst[0] = f2tf32(v.x); dst[1] = f2tf32(v.y);
            dst[2] = f2tf32(v.z); dst[3] = f2tf32(v.w);
        }
        __syncthreads();

        #pragma unroll
        for (int kk = 0; kk < 2; kk++) {
            unsigned a[2][4], b[4][2];
            #pragma unroll
            for (int mt = 0; mt < 2; mt++) {
                int rb = wm * 32 + mt * 16 + grp;
                a[mt][0] = __float_as_uint(As[rb    ][kk * 8 + qid    ]);
                a[mt][1] = __float_as_uint(As[rb + 8][kk * 8 + qid    ]);
                a[mt][2] = __float_as_uint(As[rb    ][kk * 8 + qid + 4]);
                a[mt][3] = __float_as_uint(As[rb + 8][kk * 8 + qid + 4]);
            }
            #pragma unroll
            for (int nt = 0; nt < 4; nt++) {
                int nb = wn * 32 + nt * 8 + grp;
                b[nt][0] = __float_as_uint(Bs[nb][kk * 8 + qid    ]);
                b[nt][1] = __float_as_uint(Bs[nb][kk * 8 + qid + 4]);
            }
            #pragma unroll
            for (int mt = 0; mt < 2; mt++)
                #pragma unroll
                for (int nt = 0; nt < 4; nt++)
                    mma_tf32(c[mt][nt], a[mt][0], a[mt][1], a[mt][2], a[mt][3],
                             b[nt][0], b[nt][1]);
        }
        __syncthreads();
    }

    #pragma unroll
    for (int mt = 0; mt < 2; mt++) {
        #pragma unroll
        for (int nt = 0; nt < 4; nt++) {
            int m = m0 + wm * 32 + mt * 16 + grp;
            int n = n0 + wn * 32 + nt * 8 + qid * 2;
            #pragma unroll
            for (int halfm = 0; halfm < 2; halfm++) {
                int mm = m + halfm * 8;
                float v0 = c[mt][nt][halfm * 2 + 0];
                float v1 = c[mt][nt][halfm * 2 + 1];
                if (mm < Mreal) {
                    size_t row = (size_t)mm * ldout;
                    if (n     < Nreal) out[row + n    ] = v0;
                    if (n + 1 < Nreal) out[row + n + 1] = v1;
                }
            }
        }
    }
}

// ---------------- attention logits: alpha, beta per (b,t) ----------------
__global__ void __launch_bounds__(64)
attn_logits_kernel(const float* __restrict__ Wh)
{
    const int t  = blockIdx.x;
    const int b  = blockIdx.y;
    const int bt = b * TDIM + t;
    const int tid = threadIdx.x;

    __shared__ float cvsh[KQ * KQ];
    __shared__ float gsh[KQ], cssh[KQ], whsh[64];
    __shared__ float zsh[64], red[64];

    for (int i = tid; i < KQ * KQ; i += 64) {
        int k = i / KQ, j = i - k * KQ;
        size_t base = (size_t)(b * KQ + k) * 64 + j;
        cvsh[i] = g_cv[base] + g_cv[base + CV_SLICE]
                + g_cv[base + 2 * CV_SLICE] + g_cv[base + 3 * CV_SLICE];
    }
    if (tid < KQ) {
        gsh[tid]  = g_g [(size_t)bt * 64 + tid];
        cssh[tid] = g_cs[(size_t)bt * 64 + tid];
    }
    whsh[tid] = (tid < KQ) ? Wh[tid] : 0.f;
    __syncthreads();

    // z_ext = sum_j tanh(cs_j + g_j) * Wh_j
    float e = 0.f;
    if (tid < KQ) e = tanh_fast(cssh[tid] + gsh[tid]) * whsh[tid];
    red[tid] = e;
    __syncthreads();
    for (int s = 32; s > 0; s >>= 1) {
        if (tid < s) red[tid] += red[tid + s];
        __syncthreads();
    }
    float zx = red[0];
    __syncthreads();

    // z_k = sum_j tanh(cv[b,k,j] + g_j) * Wh_j
    float z = -1e30f;
    if (tid < KQ) {
        float acc = 0.f;
        const float* cvr = &cvsh[tid * KQ];
        #pragma unroll 7
        for (int j = 0; j < KQ; j++)
            acc += tanh_fast(cvr[j] + gsh[j]) * whsh[j];
        z = acc;
    }
    zsh[tid] = z;
    red[tid] = z;
    __syncthreads();
    for (int s = 32; s > 0; s >>= 1) {
        if (tid < s) red[tid] = fmaxf(red[tid], red[tid + s]);
        __syncthreads();
    }
    float mx = red[0];
    __syncthreads();

    float ez = (tid < KQ) ? expf(zsh[tid] - mx) : 0.f;
    red[tid] = ez;
    __syncthreads();
    for (int s = 32; s > 0; s >>= 1) {
        if (tid < s) red[tid] += red[tid + s];
        __syncthreads();
    }
    float sum49 = red[0];

    if (tid < KQ) g_al[(size_t)bt * 64 + tid] = ez / sum49;
    if (tid == 0) {
        float M2 = fmaxf(mx, zx);
        float denom = expf(mx - M2) * sum49 + expf(zx - M2);
        g_be[bt] = expf(zx - M2) / denom;
    }
}

// ---------------- final: out = beta*s_t + (1-beta)*(alpha@V) + hiddens ------
__global__ void __launch_bounds__(256)
final_kernel(const float* __restrict__ V, const float* __restrict__ hiddens,
             float* __restrict__ out)
{
    const int b  = blockIdx.z;
    const int t0 = blockIdx.y * 16;
    const int h0 = blockIdx.x * 256;
    const int tid  = threadIdx.x;
    const int hthr = tid & 63;
    const int tthr = tid >> 6;

    __shared__ float al[16][52];
    __shared__ float be[16];

    for (int i = tid; i < 16 * KQ; i += 256) {
        int tt = i / KQ, k = i - tt * KQ;
        al[tt][k] = g_al[(size_t)(b * TDIM + t0 + tt) * 64 + k];
    }
    if (tid < 16) be[tid] = g_be[b * TDIM + t0 + tid];
    __syncthreads();

    const int h = h0 + hthr * 4;
    float4 acc[4];
    #pragma unroll
    for (int i = 0; i < 4; i++) acc[i] = make_float4(0.f, 0.f, 0.f, 0.f);

    const float* Vb = V + (size_t)b * KQ * HDIM + h;
    for (int k = 0; k < KQ; k++) {
        float4 v = *(const float4*)(Vb + (size_t)k * HDIM);
        #pragma unroll
        for (int i = 0; i < 4; i++) {
            float a = al[tthr * 4 + i][k];
            acc[i].x += a * v.x; acc[i].y += a * v.y;
            acc[i].z += a * v.z; acc[i].w += a * v.w;
        }
    }
    #pragma unroll
    for (int i = 0; i < 4; i++) {
        int t = t0 + tthr * 4 + i;
        size_t idx = ((size_t)(b * TDIM + t)) * HDIM + h;
        uint2 su = *(const uint2*)(g_st + idx);       // 4 fp16
        float2 s01 = __half22float2(*(__half2*)&su.x);
        float2 s23 = __half22float2(*(__half2*)&su.y);
        float4 hd = *(const float4*)(hiddens + idx);
        float bt = be[tthr * 4 + i];
        float om = 1.f - bt;
        float4 o;
        o.x = bt * s01.x + om * acc[i].x + hd.x;
        o.y = bt * s01.y + om * acc[i].y + hd.y;
        o.z = bt * s23.x + om * acc[i].z + hd.z;
        o.w = bt * s23.y + om * acc[i].w + hd.w;
        *(float4*)(out + idx) = o;
    }
}

// ---------------- launch ----------------
extern "C" void kernel_launch(void* const* d_in, const int* in_sizes, int n_in,
                              void* d_out, int out_size)
{
    const float* x       = (const float*)d_in[0];
    const float* hiddens = (const float*)d_in[1];
    const float* cells   = (const float*)d_in[2];
    const float* V       = (const float*)d_in[3];
    const float* Wx      = (const float*)d_in[4];
    // d_in[5] = Whh, unused: h_prev == 0 so its contribution is exactly zero.
    const float* Wv      = (const float*)d_in[6];
    const float* Wg      = (const float*)d_in[7];
    const float* Ws      = (const float*)d_in[8];
    const float* Wh      = (const float*)d_in[9];
    float* out = (float*)d_out;

    __half* p_st; __nv_bfloat16 *p_xb, *p_wb;
    float *p_g, *p_cs, *p_cv;
    cudaGetSymbolAddress((void**)&p_st, g_st);
    cudaGetSymbolAddress((void**)&p_xb, g_xb);
    cudaGetSymbolAddress((void**)&p_wb, g_wb);
    cudaGetSymbolAddress((void**)&p_g,  g_g);
    cudaGetSymbolAddress((void**)&p_cs, g_cs);
    cudaGetSymbolAddress((void**)&p_cv, g_cv);

    // x, Wx -> bf16 (one pass each)
    cvt_bf16_kernel<<<(MT_ROWS * HDIM / 4 + 255) / 256, 256>>>(x, p_xb,
                                                               MT_ROWS * HDIM / 4);
    cvt_bf16_kernel<<<(HDIM * HDIM / 4 + 255) / 256, 256>>>(Wx, p_wb,
                                                            HDIM * HDIM / 4);

    // s_t = sigmoid(x @ Wx^T) * tanh(cells)  [32768 x 1024], bf16 HMMA
    gemm1_bf16_kernel<<<dim3(8, 256), 256>>>(cells);
    // g = hiddens @ Wg^T                     [32768 x 49]
    gemm_thin_kernel<false><<<dim3(1, 256, 1), 256>>>(hiddens, Wg, p_g,
                                                      MT_ROWS, KQ, 64, 0);
    // cs = s_t @ Ws^T                        [32768 x 49]  (s_t fp16)
    gemm_thin_kernel<true><<<dim3(1, 256, 1), 256>>>(p_st, Ws, p_cs,
                                                     MT_ROWS, KQ, 64, 0);
    // cv = V @ Wv^T  (V as [3136, 1024]), K-split x4 into partial slices
    gemm_thin_kernel<false><<<dim3(1, 25, 4), 256>>>(V, Wv, p_cv,
                                                     3136, KQ, 64, CV_SLICE);
    // alpha / beta per (b,t)
    attn_logits_kernel<<<dim3(TDIM, BDIM), 64>>>(Wh);
    // out = beta*s_t + (1-beta)*(alpha@V) + hiddens
    final_kernel<<<dim3(4, 32, 64), 256>>>(V, hiddens, out);
}

// round 15
// speedup vs baseline: 2.1296x; 1.2100x over previous
#include <cuda_runtime.h>
#include <cuda_fp16.h>
#include <cuda_bf16.h>
#include <math.h>
#include <stdint.h>

// Problem dims (fixed by the reference)
#define BDIM 64
#define TDIM 512
#define HDIM 1024
#define KQ   49
#define MT_ROWS (BDIM*TDIM)   // 32768

// ---------------- static scratch (no allocs allowed) ----------------
__device__ __half g_st[33554432];              // s_t  [B*T, H] fp16 (64 MB)
__device__ __nv_bfloat16 g_xb[33554432];       // x in bf16      (64 MB)
__device__ __nv_bfloat16 g_wb[HDIM * HDIM];    // Wx in bf16     (2 MB)
__device__ float g_g [MT_ROWS * 64];           // g   [B*T, 49] padded to 64
__device__ float g_cs[MT_ROWS * 64];           // content_s raw (s_t@Ws^T)
__device__ float g_cv[4 * 3200 * 64];          // cv partials (4 K-slices)
__device__ float g_al[MT_ROWS * 64];           // alpha [B*T, 49] padded
__device__ float g_be[MT_ROWS];                // beta  [B*T]

#define CV_SLICE (3200 * 64)

// ---------------- fast math helpers ----------------
__device__ __forceinline__ float tanh_fast(float x){
    float y; asm("tanh.approx.f32 %0, %1;" : "=f"(y) : "f"(x)); return y;
}
__device__ __forceinline__ unsigned pack_f16(float lo, float hi){
    unsigned r; asm("cvt.rn.f16x2.f32 %0, %1, %2;" : "=r"(r) : "f"(hi), "f"(lo)); return r;
}
__device__ __forceinline__ unsigned pack_bf16(float lo, float hi){
    unsigned r; asm("cvt.rn.bf16x2.f32 %0, %1, %2;" : "=r"(r) : "f"(hi), "f"(lo)); return r;
}
__device__ __forceinline__ uint32_t smem_u32(const void* p) {
    uint32_t a;
    asm("{ .reg .u64 t; cvta.to.shared.u64 t, %1; cvt.u32.u64 %0, t; }"
        : "=r"(a) : "l"(p));
    return a;
}
__device__ __forceinline__ void ldsm_x4(unsigned &r0, unsigned &r1,
                                        unsigned &r2, unsigned &r3, uint32_t addr){
    asm volatile("ldmatrix.sync.aligned.m8n8.x4.shared.b16 {%0,%1,%2,%3}, [%4];"
        : "=r"(r0), "=r"(r1), "=r"(r2), "=r"(r3) : "r"(addr));
}

// ---------------- fp32 -> bf16 conversion pass ----------------
__global__ void __launch_bounds__(256)
cvt_bf16_kernel(const float* __restrict__ src, __nv_bfloat16* __restrict__ dst,
                int n4)
{
    int i = blockIdx.x * 256 + threadIdx.x;
    if (i < n4) {
        float4 v = ((const float4*)src)[i];
        uint2 p;
        p.x = pack_bf16(v.x, v.y);
        p.y = pack_bf16(v.z, v.w);
        ((uint2*)dst)[i] = p;
    }
}

// ================= GEMM1: bf16 mma.sync m16n8k16 =================
// s_t = sigmoid(x @ Wx^T) * tanh(cells), stored fp16.
// BM=128, BN=128, BK=32. 8 warps (2m x 4n), warp tile 64x32.
// Double-buffered smem, register-staged prefetch, ldmatrix fragment loads.
#define G1_ROWW 20                 // words per smem row (32 bf16 = 16 words + pad)
#define G1_BUFW (128 * G1_ROWW)    // 2560 words per matrix per buffer

__device__ __forceinline__ void mma_bf16(float c[4], const unsigned a[4],
                                         const unsigned b[2]){
    asm volatile(
        "mma.sync.aligned.m16n8k16.row.col.f32.bf16.bf16.f32 "
        "{%0,%1,%2,%3}, {%4,%5,%6,%7}, {%8,%9}, {%0,%1,%2,%3};\n"
        : "+f"(c[0]), "+f"(c[1]), "+f"(c[2]), "+f"(c[3])
        : "r"(a[0]), "r"(a[1]), "r"(a[2]), "r"(a[3]), "r"(b[0]), "r"(b[1]));
}

__global__ void __launch_bounds__(256, 2)
gemm1_bf16_kernel(const float* __restrict__ cells)
{
    __shared__ __align__(16) unsigned As[2][G1_BUFW];
    __shared__ __align__(16) unsigned Bs[2][G1_BUFW];

    const int tid  = threadIdx.x;
    const int lane = tid & 31;
    const int warp = tid >> 5;
    const int grp  = lane >> 2;     // 0..7
    const int qid  = lane & 3;      // 0..3
    const int wm   = warp >> 2;     // 0..1
    const int wn   = warp & 3;      // 0..3

    const int m0 = blockIdx.y * 128;
    const int n0 = blockIdx.x * 128;

    // load chunk mapping: 512 uint4 chunks (128 rows x 4 chunks of 8 bf16), 2/thr
    const int r0 = tid >> 2,         cg0 = tid & 3;
    const int r1 = (tid + 256) >> 2, cg1 = (tid + 256) & 3;

    const __nv_bfloat16* __restrict__ xb = g_xb;
    const __nv_bfloat16* __restrict__ wb = g_wb;

    // ldmatrix lane addresses
    const uint32_t As_sm = smem_u32(&As[0][0]);
    const uint32_t Bs_sm = smem_u32(&Bs[0][0]);
    const int arow = lane & 15;
    const uint32_t a_off = ((wm * 64 + arow) * G1_ROWW + ((lane >> 4) << 2)) * 4;
    const int brow = (lane & 7) | ((lane >> 4) << 3);
    const uint32_t b_off = ((wn * 32 + brow) * G1_ROWW + (((lane >> 3) & 1) << 2)) * 4;

    float c[4][4][4];
    #pragma unroll
    for (int i = 0; i < 4; i++)
        #pragma unroll
        for (int j = 0; j < 4; j++)
            #pragma unroll
            for (int r = 0; r < 4; r++) c[i][j][r] = 0.f;

    // ---- prologue: load tile 0 ---- (chunk = 8 bf16 elements = one uint4)
    {
        uint4 a0 = *(const uint4*)(xb + (size_t)(m0 + r0) * HDIM + cg0 * 8);
        uint4 a1 = *(const uint4*)(xb + (size_t)(m0 + r1) * HDIM + cg1 * 8);
        uint4 b0 = *(const uint4*)(wb + (size_t)(n0 + r0) * HDIM + cg0 * 8);
        uint4 b1 = *(const uint4*)(wb + (size_t)(n0 + r1) * HDIM + cg1 * 8);
        *(uint4*)(&As[0][r0 * G1_ROWW + cg0 * 4]) = a0;
        *(uint4*)(&As[0][r1 * G1_ROWW + cg1 * 4]) = a1;
        *(uint4*)(&Bs[0][r0 * G1_ROWW + cg0 * 4]) = b0;
        *(uint4*)(&Bs[0][r1 * G1_ROWW + cg1 * 4]) = b1;
    }
    __syncthreads();

    for (int kt = 0; kt < 32; kt++) {
        const uint32_t bufoff = (uint32_t)(kt & 1) * (G1_BUFW * 4);

        uint4 a0, a1, b0, b1;
        if (kt < 31) {
            const int k0 = (kt + 1) * 32;
            a0 = *(const uint4*)(xb + (size_t)(m0 + r0) * HDIM + k0 + cg0 * 8);
            a1 = *(const uint4*)(xb + (size_t)(m0 + r1) * HDIM + k0 + cg1 * 8);
            b0 = *(const uint4*)(wb + (size_t)(n0 + r0) * HDIM + k0 + cg0 * 8);
            b1 = *(const uint4*)(wb + (size_t)(n0 + r1) * HDIM + k0 + cg1 * 8);
        }

        #pragma unroll
        for (int kk = 0; kk < 2; kk++) {
            unsigned af[4][4], bf[4][2];
            #pragma unroll
            for (int mt = 0; mt < 4; mt++)
                ldsm_x4(af[mt][0], af[mt][1], af[mt][2], af[mt][3],
                        As_sm + bufoff + a_off + mt * (16 * G1_ROWW * 4) + kk * 32);
            ldsm_x4(bf[0][0], bf[0][1], bf[1][0], bf[1][1],
                    Bs_sm + bufoff + b_off + kk * 32);
            ldsm_x4(bf[2][0], bf[2][1], bf[3][0], bf[3][1],
                    Bs_sm + bufoff + b_off + 16 * G1_ROWW * 4 + kk * 32);
            #pragma unroll
            for (int mt = 0; mt < 4; mt++)
                #pragma unroll
                for (int nt = 0; nt < 4; nt++)
                    mma_bf16(c[mt][nt], af[mt], bf[nt]);
        }

        if (kt < 31) {
            unsigned* An = As[(kt + 1) & 1];
            unsigned* Bn = Bs[(kt + 1) & 1];
            *(uint4*)(&An[r0 * G1_ROWW + cg0 * 4]) = a0;
            *(uint4*)(&An[r1 * G1_ROWW + cg1 * 4]) = a1;
            *(uint4*)(&Bn[r0 * G1_ROWW + cg0 * 4]) = b0;
            *(uint4*)(&Bn[r1 * G1_ROWW + cg1 * 4]) = b1;
        }
        __syncthreads();
    }

    // ---- epilogue: sigmoid(y)*tanh(cells) -> fp16 s_t ----
    #pragma unroll
    for (int mt = 0; mt < 4; mt++) {
        #pragma unroll
        for (int nt = 0; nt < 4; nt++) {
            const int m = m0 + wm * 64 + mt * 16 + grp;
            const int n = n0 + wn * 32 + nt * 8 + qid * 2;
            #pragma unroll
            for (int half = 0; half < 2; half++) {
                const int mm = m + half * 8;
                const float y0 = c[mt][nt][half * 2 + 0];
                const float y1 = c[mt][nt][half * 2 + 1];
                const size_t idx = (size_t)mm * HDIM + n;
                const float2 cl = *(const float2*)(cells + idx);
                const float gate0 = 0.5f + 0.5f * tanh_fast(0.5f * y0);
                const float gate1 = 0.5f + 0.5f * tanh_fast(0.5f * y1);
                const float s0 = gate0 * tanh_fast(cl.x);
                const float s1 = gate1 * tanh_fast(cl.y);
                *(unsigned*)(&g_st[idx]) = pack_f16(s0, s1);
            }
        }
    }
}

// ================= thin tf32 GEMM (g / cs / cv), double-buffered =================
__device__ __forceinline__ unsigned f2tf32(float x){
    unsigned u; asm("cvt.rna.tf32.f32 %0, %1;" : "=r"(u) : "f"(x)); return u;
}
__device__ __forceinline__ void mma_tf32(float c[4],
        unsigned a0, unsigned a1, unsigned a2, unsigned a3,
        unsigned b0, unsigned b1){
    asm volatile(
        "mma.sync.aligned.m16n8k8.row.col.f32.tf32.tf32.f32 "
        "{%0,%1,%2,%3}, {%4,%5,%6,%7}, {%8,%9}, {%0,%1,%2,%3};\n"
        : "+f"(c[0]), "+f"(c[1]), "+f"(c[2]), "+f"(c[3])
        : "r"(a0), "r"(a1), "r"(a2), "r"(a3), "r"(b0), "r"(b1));
}

// out[m,n] = sum_{k in slice} A[m,k]*Bm[n,k]; AHALF: A is fp16.
// K-split over gridDim.z; slice z writes to out + z*pstride.
template<bool AHALF>
__global__ void __launch_bounds__(256, 2)
gemm_thin_kernel(const void* __restrict__ Ain, const float* __restrict__ Bm,
                 float* __restrict__ out, int Mreal, int Nreal, int ldout,
                 long long pstride)
{
    __shared__ __align__(16) float As[2][128][20];
    __shared__ __align__(16) float Bs[2][64][20];

    const int kper = HDIM / gridDim.z;
    const int kb = blockIdx.z * kper;
    const int ke = kb + kper;
    out += (long long)blockIdx.z * pstride;

    const int tid  = threadIdx.x;
    const int lane = tid & 31;
    const int warp = tid >> 5;
    const int grp  = lane >> 2;
    const int qid  = lane & 3;
    const int wm   = warp >> 1;
    const int wn   = warp & 1;
    const int m0 = blockIdx.y * 128;
    const int n0 = blockIdx.x * 64;
    const int lrow = tid >> 2;
    const int lq   = tid & 3;

    float c[2][4][4];
    #pragma unroll
    for (int i = 0; i < 2; i++)
        #pragma unroll
        for (int j = 0; j < 4; j++)
            #pragma unroll
            for (int r = 0; r < 4; r++) c[i][j][r] = 0.f;

    // load one A row-chunk of 4 floats (handles fp16 A)
    auto loadA = [&](int m, int k0) -> float4 {
        float4 v = make_float4(0.f, 0.f, 0.f, 0.f);
        if (m < Mreal) {
            if (AHALF) {
                const __half* A = (const __half*)Ain;
                uint2 u = *(const uint2*)(A + (size_t)m * HDIM + k0 + lq * 4);
                float2 f0 = __half22float2(*(__half2*)&u.x);
                float2 f1 = __half22float2(*(__half2*)&u.y);
                v = make_float4(f0.x, f0.y, f1.x, f1.y);
            } else {
                const float* A = (const float*)Ain;
                v = *(const float4*)(A + (size_t)m * HDIM + k0 + lq * 4);
            }
        }
        return v;
    };
    auto stsA = [&](int buf, int r, float4 v) {
        unsigned* dst = (unsigned*)&As[buf][r][lq * 4];
        dst[0] = f2tf32(v.x); dst[1] = f2tf32(v.y);
        dst[2] = f2tf32(v.z); dst[3] = f2tf32(v.w);
    };

    // prologue: tile kb -> buf 0
    {
        stsA(0, lrow,      loadA(m0 + lrow,      kb));
        stsA(0, lrow + 64, loadA(m0 + lrow + 64, kb));
        float4 v = make_float4(0.f, 0.f, 0.f, 0.f);
        if (n0 + lrow < Nreal)
            v = *(const float4*)(Bm + (size_t)(n0 + lrow) * HDIM + kb + lq * 4);
        unsigned* dst = (unsigned*)&Bs[0][lrow][lq * 4];
        dst[0] = f2tf32(v.x); dst[1] = f2tf32(v.y);
        dst[2] = f2tf32(v.z); dst[3] = f2tf32(v.w);
    }
    __syncthreads();

    for (int k0 = kb; k0 < ke; k0 += 16) {
        const int cur = ((k0 - kb) >> 4) & 1;
        const bool have = (k0 + 16 < ke);

        float4 va0, va1, vb;
        if (have) {
            va0 = loadA(m0 + lrow,      k0 + 16);
            va1 = loadA(m0 + lrow + 64, k0 + 16);
            vb = make_float4(0.f, 0.f, 0.f, 0.f);
            if (n0 + lrow < Nreal)
                vb = *(const float4*)(Bm + (size_t)(n0 + lrow) * HDIM + k0 + 16 + lq * 4);
        }

        #pragma unroll
        for (int kk = 0; kk < 2; kk++) {
            unsigned a[2][4], b[4][2];
            #pragma unroll
            for (int mt = 0; mt < 2; mt++) {
                int rb = wm * 32 + mt * 16 + grp;
                a[mt][0] = __float_as_uint(As[cur][rb    ][kk * 8 + qid    ]);
                a[mt][1] = __float_as_uint(As[cur][rb + 8][kk * 8 + qid    ]);
                a[mt][2] = __float_as_uint(As[cur][rb    ][kk * 8 + qid + 4]);
                a[mt][3] = __float_as_uint(As[cur][rb + 8][kk * 8 + qid + 4]);
            }
            #pragma unroll
            for (int nt = 0; nt < 4; nt++) {
                int nb = wn * 32 + nt * 8 + grp;
                b[nt][0] = __float_as_uint(Bs[cur][nb][kk * 8 + qid    ]);
                b[nt][1] = __float_as_uint(Bs[cur][nb][kk * 8 + qid + 4]);
            }
            #pragma unroll
            for (int mt = 0; mt < 2; mt++)
                #pragma unroll
                for (int nt = 0; nt < 4; nt++)
                    mma_tf32(c[mt][nt], a[mt][0], a[mt][1], a[mt][2], a[mt][3],
                             b[nt][0], b[nt][1]);
        }

        if (have) {
            const int nb = cur ^ 1;
            stsA(nb, lrow, va0);
            stsA(nb, lrow + 64, va1);
            unsigned* dst = (unsigned*)&Bs[nb][lrow][lq * 4];
            dst[0] = f2tf32(vb.x); dst[1] = f2tf32(vb.y);
            dst[2] = f2tf32(vb.z); dst[3] = f2tf32(vb.w);
        }
        __syncthreads();
    }

    #pragma unroll
    for (int mt = 0; mt < 2; mt++) {
        #pragma unroll
        for (int nt = 0; nt < 4; nt++) {
            int m = m0 + wm * 32 + mt * 16 + grp;
            int n = n0 + wn * 32 + nt * 8 + qid * 2;
            #pragma unroll
            for (int halfm = 0; halfm < 2; halfm++) {
                int mm = m + halfm * 8;
                float v0 = c[mt][nt][halfm * 2 + 0];
                float v1 = c[mt][nt][halfm * 2 + 1];
                if (mm < Mreal) {
                    size_t row = (size_t)mm * ldout;
                    if (n     < Nreal) out[row + n    ] = v0;
                    if (n + 1 < Nreal) out[row + n + 1] = v1;
                }
            }
        }
    }
}

// ---------------- attention logits: block per (b, 64-t chunk) ----------------
#define ATC 64
__global__ void __launch_bounds__(256)
attn_logits_kernel(const float* __restrict__ Wh)
{
    const int b  = blockIdx.y;
    const int t0 = blockIdx.x * ATC;
    const int tid = threadIdx.x;

    __shared__ float cvsh[KQ * KQ];        // [k][j], summed partials
    __shared__ float whsh[KQ];
    __shared__ float gsh[ATC][KQ + 1];
    __shared__ float cssh[ATC][KQ + 1];
    __shared__ float zsh[ATC][51];
    __shared__ float inv_s[ATC];

    for (int i = tid; i < KQ * KQ; i += 256) {
        int k = i / KQ, j = i - k * KQ;
        size_t base = (size_t)(b * KQ + k) * 64 + j;
        cvsh[i] = g_cv[base] + g_cv[base + CV_SLICE]
                + g_cv[base + 2 * CV_SLICE] + g_cv[base + 3 * CV_SLICE];
    }
    if (tid < KQ) whsh[tid] = Wh[tid];
    for (int i = tid; i < ATC * KQ; i += 256) {
        int t = i / KQ, j = i - t * KQ;
        size_t base = (size_t)(b * TDIM + t0 + t) * 64 + j;
        gsh[t][j]  = g_g [base];
        cssh[t][j] = g_cs[base];
    }
    __syncthreads();

    // 64*50 dot-products of length 49
    for (int idx = tid; idx < ATC * 50; idx += 256) {
        const int t = idx / 50, k = idx - t * 50;
        const float* row = (k < 49) ? &cvsh[k * KQ] : &cssh[t][0];
        const float* gr  = &gsh[t][0];
        float acc = 0.f;
        #pragma unroll 7
        for (int j = 0; j < KQ; j++)
            acc += tanh_fast(row[j] + gr[j]) * whsh[j];
        zsh[t][k] = acc;
    }
    __syncthreads();

    // per-t softmax (alpha over 49, beta from extended 50)
    if (tid < ATC) {
        const int t = tid;
        float mx = -1e30f;
        #pragma unroll 7
        for (int j = 0; j < KQ; j++) mx = fmaxf(mx, zsh[t][j]);
        float s = 0.f;
        #pragma unroll 7
        for (int j = 0; j < KQ; j++) {
            float e = __expf(zsh[t][j] - mx);
            zsh[t][j] = e; s += e;
        }
        inv_s[t] = 1.f / s;
        const float zx = zsh[t][49];
        const float M2 = fmaxf(mx, zx);
        const float denom = __expf(mx - M2) * s + __expf(zx - M2);
        g_be[b * TDIM + t0 + t] = __expf(zx - M2) / denom;
    }
    __syncthreads();

    // coalesced alpha writeback
    for (int i = tid; i < ATC * KQ; i += 256) {
        int t = i / KQ, j = i - t * KQ;
        g_al[(size_t)(b * TDIM + t0 + t) * 64 + j] = zsh[t][j] * inv_s[t];
    }
}

// ---------------- final: out = beta*s_t + (1-beta)*(alpha@V) + hiddens ------
__global__ void __launch_bounds__(256)
final_kernel(const float* __restrict__ V, const float* __restrict__ hiddens,
             float* __restrict__ out)
{
    const int b  = blockIdx.z;
    const int t0 = blockIdx.y * 16;
    const int h0 = blockIdx.x * 256;
    const int tid  = threadIdx.x;
    const int hthr = tid & 63;
    const int tthr = tid >> 6;

    __shared__ float al[16][52];
    __shared__ float be[16];

    for (int i = tid; i < 16 * KQ; i += 256) {
        int tt = i / KQ, k = i - tt * KQ;
        al[tt][k] = g_al[(size_t)(b * TDIM + t0 + tt) * 64 + k];
    }
    if (tid < 16) be[tid] = g_be[b * TDIM + t0 + tid];
    __syncthreads();

    const int h = h0 + hthr * 4;
    float4 acc[4];
    #pragma unroll
    for (int i = 0; i < 4; i++) acc[i] = make_float4(0.f, 0.f, 0.f, 0.f);

    const float* Vb = V + (size_t)b * KQ * HDIM + h;
    for (int k = 0; k < KQ; k++) {
        float4 v = *(const float4*)(Vb + (size_t)k * HDIM);
        #pragma unroll
        for (int i = 0; i < 4; i++) {
            float a = al[tthr * 4 + i][k];
            acc[i].x += a * v.x; acc[i].y += a * v.y;
            acc[i].z += a * v.z; acc[i].w += a * v.w;
        }
    }
    #pragma unroll
    for (int i = 0; i < 4; i++) {
        int t = t0 + tthr * 4 + i;
        size_t idx = ((size_t)(b * TDIM + t)) * HDIM + h;
        uint2 su = *(const uint2*)(g_st + idx);       // 4 fp16
        float2 s01 = __half22float2(*(__half2*)&su.x);
        float2 s23 = __half22float2(*(__half2*)&su.y);
        float4 hd = *(const float4*)(hiddens + idx);
        float bt = be[tthr * 4 + i];
        float om = 1.f - bt;
        float4 o;
        o.x = bt * s01.x + om * acc[i].x + hd.x;
        o.y = bt * s01.y + om * acc[i].y + hd.y;
        o.z = bt * s23.x + om * acc[i].z + hd.z;
        o.w = bt * s23.y + om * acc[i].w + hd.w;
        *(float4*)(out + idx) = o;
    }
}

// ---------------- launch ----------------
extern "C" void kernel_launch(void* const* d_in, const int* in_sizes, int n_in,
                              void* d_out, int out_size)
{
    const float* x       = (const float*)d_in[0];
    const float* hiddens = (const float*)d_in[1];
    const float* cells   = (const float*)d_in[2];
    const float* V       = (const float*)d_in[3];
    const float* Wx      = (const float*)d_in[4];
    // d_in[5] = Whh, unused: h_prev == 0 so its contribution is exactly zero.
    const float* Wv      = (const float*)d_in[6];
    const float* Wg      = (const float*)d_in[7];
    const float* Ws      = (const float*)d_in[8];
    const float* Wh      = (const float*)d_in[9];
    float* out = (float*)d_out;

    __half* p_st; __nv_bfloat16 *p_xb, *p_wb;
    float *p_g, *p_cs, *p_cv;
    cudaGetSymbolAddress((void**)&p_st, g_st);
    cudaGetSymbolAddress((void**)&p_xb, g_xb);
    cudaGetSymbolAddress((void**)&p_wb, g_wb);
    cudaGetSymbolAddress((void**)&p_g,  g_g);
    cudaGetSymbolAddress((void**)&p_cs, g_cs);
    cudaGetSymbolAddress((void**)&p_cv, g_cv);

    // x, Wx -> bf16 (one pass each)
    cvt_bf16_kernel<<<(MT_ROWS * HDIM / 4 + 255) / 256, 256>>>(x, p_xb,
                                                               MT_ROWS * HDIM / 4);
    cvt_bf16_kernel<<<(HDIM * HDIM / 4 + 255) / 256, 256>>>(Wx, p_wb,
                                                            HDIM * HDIM / 4);

    // s_t = sigmoid(x @ Wx^T) * tanh(cells)  [32768 x 1024], bf16 HMMA
    gemm1_bf16_kernel<<<dim3(8, 256), 256>>>(cells);
    // g = hiddens @ Wg^T                     [32768 x 49]
    gemm_thin_kernel<false><<<dim3(1, 256, 1), 256>>>(hiddens, Wg, p_g,
                                                      MT_ROWS, KQ, 64, 0);
    // cs = s_t @ Ws^T                        [32768 x 49]  (s_t fp16)
    gemm_thin_kernel<true><<<dim3(1, 256, 1), 256>>>(p_st, Ws, p_cs,
                                                     MT_ROWS, KQ, 64, 0);
    // cv = V @ Wv^T  (V as [3136, 1024]), K-split x4 into partial slices
    gemm_thin_kernel<false><<<dim3(1, 25, 4), 256>>>(V, Wv, p_cv,
                                                     3136, KQ, 64, CV_SLICE);
    // alpha / beta per (b, 64-t chunk)
    attn_logits_kernel<<<dim3(TDIM / ATC, BDIM), 256>>>(Wh);
    // out = beta*s_t + (1-beta)*(alpha@V) + hiddens
    final_kernel<<<dim3(4, 32, 64), 256>>>(V, hiddens, out);
}

// round 16
// speedup vs baseline: 2.5106x; 1.1789x over previous
#include <cuda_runtime.h>
#include <cuda_fp16.h>
#include <cuda_bf16.h>
#include <math.h>
#include <stdint.h>

// Problem dims (fixed by the reference)
#define BDIM 64
#define TDIM 512
#define HDIM 1024
#define KQ   49
#define MT_ROWS (BDIM*TDIM)   // 32768

// ---------------- static scratch (no allocs allowed) ----------------
__device__ __half g_st[33554432];              // s_t  [B*T, H] fp16 (64 MB)
__device__ __nv_bfloat16 g_xb[33554432];       // x in bf16      (64 MB)
__device__ __nv_bfloat16 g_wb[HDIM * HDIM];    // Wx in bf16     (2 MB)
__device__ __half g_wsh[64 * HDIM];            // Ws fp16, zero-padded to 64 rows
__device__ float g_g [MT_ROWS * 64];           // g   [B*T, 49] padded to 64
__device__ float g_cs[MT_ROWS * 64];           // content_s raw (s_t@Ws^T)
__device__ float g_cv[4 * 3200 * 64];          // cv partials (4 K-slices)
__device__ float g_al[MT_ROWS * 64];           // alpha [B*T, 49] padded
__device__ float g_be[MT_ROWS];                // beta  [B*T]

#define CV_SLICE (3200 * 64)

// ---------------- helpers ----------------
__device__ __forceinline__ float tanh_fast(float x){
    float y; asm("tanh.approx.f32 %0, %1;" : "=f"(y) : "f"(x)); return y;
}
__device__ __forceinline__ unsigned pack_f16(float lo, float hi){
    unsigned r; asm("cvt.rn.f16x2.f32 %0, %1, %2;" : "=r"(r) : "f"(hi), "f"(lo)); return r;
}
__device__ __forceinline__ unsigned pack_bf16(float lo, float hi){
    unsigned r; asm("cvt.rn.bf16x2.f32 %0, %1, %2;" : "=r"(r) : "f"(hi), "f"(lo)); return r;
}
__device__ __forceinline__ uint32_t smem_u32(const void* p) {
    uint32_t a;
    asm("{ .reg .u64 t; cvta.to.shared.u64 t, %1; cvt.u32.u64 %0, t; }"
        : "=r"(a) : "l"(p));
    return a;
}
__device__ __forceinline__ void ldsm_x4(unsigned &r0, unsigned &r1,
                                        unsigned &r2, unsigned &r3, uint32_t addr){
    asm volatile("ldmatrix.sync.aligned.m8n8.x4.shared.b16 {%0,%1,%2,%3}, [%4];"
        : "=r"(r0), "=r"(r1), "=r"(r2), "=r"(r3) : "r"(addr));
}
#define CP16(dst, src) \
    asm volatile("cp.async.cg.shared.global [%0], [%1], 16;" :: "r"(dst), "l"(src))
#define CP16P(dst, src, sz) \
    asm volatile("cp.async.cg.shared.global [%0], [%1], 16, %2;" :: "r"(dst), "l"(src), "r"(sz))
#define CP_COMMIT() asm volatile("cp.async.commit_group;" ::: "memory")
#define CP_WAIT1()  asm volatile("cp.async.wait_group 1;" ::: "memory")
#define CP_WAIT2()  asm volatile("cp.async.wait_group 2;" ::: "memory")

// ---------------- fp32 -> bf16 conversion pass ----------------
__global__ void __launch_bounds__(256)
cvt_bf16_kernel(const float* __restrict__ src, __nv_bfloat16* __restrict__ dst,
                int n4)
{
    int i = blockIdx.x * 256 + threadIdx.x;
    if (i < n4) {
        float4 v = ((const float4*)src)[i];
        uint2 p;
        p.x = pack_bf16(v.x, v.y);
        p.y = pack_bf16(v.z, v.w);
        ((uint2*)dst)[i] = p;
    }
}

// Ws (49x1024 fp32) -> fp16, zero-padded to 64 rows
__global__ void __launch_bounds__(256)
cvt_ws_kernel(const float* __restrict__ Ws, __half* __restrict__ dst)
{
    int i = blockIdx.x * 256 + threadIdx.x;   // 65536
    int row = i >> 10;
    float v = (row < KQ) ? Ws[i] : 0.f;       // i = row*1024+col valid while row<49
    dst[i] = __float2half(v);
}

// ================= GEMM1: bf16 mma.sync m16n8k16, 3-stage cp.async =========
#define G1_ROWW 20                 // words per smem row (32 bf16 = 16 words + pad)
#define G1_BUFW (128 * G1_ROWW)    // 2560 words per matrix per stage
#define G1_SMEM (6 * G1_BUFW * 4)  // 61440 bytes

__device__ __forceinline__ void mma_bf16(float c[4], const unsigned a[4],
                                         const unsigned b[2]){
    asm volatile(
        "mma.sync.aligned.m16n8k16.row.col.f32.bf16.bf16.f32 "
        "{%0,%1,%2,%3}, {%4,%5,%6,%7}, {%8,%9}, {%0,%1,%2,%3};\n"
        : "+f"(c[0]), "+f"(c[1]), "+f"(c[2]), "+f"(c[3])
        : "r"(a[0]), "r"(a[1]), "r"(a[2]), "r"(a[3]), "r"(b[0]), "r"(b[1]));
}

__global__ void __launch_bounds__(256, 2)
gemm1_bf16_kernel(const float* __restrict__ cells)
{
    extern __shared__ __align__(16) unsigned g1s[];
    unsigned* Asm = g1s;                 // 3 stages x G1_BUFW
    unsigned* Bsm = g1s + 3 * G1_BUFW;

    const int tid  = threadIdx.x;
    const int lane = tid & 31;
    const int warp = tid >> 5;
    const int grp  = lane >> 2;     // 0..7
    const int qid  = lane & 3;      // 0..3
    const int wm   = warp >> 2;     // 0..1
    const int wn   = warp & 3;      // 0..3

    const int m0 = blockIdx.y * 128;
    const int n0 = blockIdx.x * 128;

    // 512 chunks (128 rows x 4 chunks of 8 bf16) per matrix, 2 per thread
    const int r0 = tid >> 2,         cg0 = tid & 3;
    const int r1 = (tid + 256) >> 2;  // cg same as cg0

    const __nv_bfloat16* __restrict__ xb = g_xb;
    const __nv_bfloat16* __restrict__ wb = g_wb;

    const uint32_t As_sm = smem_u32(Asm);
    const uint32_t Bs_sm = smem_u32(Bsm);
    const uint32_t dA0 = (r0 * G1_ROWW + cg0 * 4) * 4;
    const uint32_t dA1 = (r1 * G1_ROWW + cg0 * 4) * 4;
    const __nv_bfloat16* sA0 = xb + (size_t)(m0 + r0) * HDIM + cg0 * 8;
    const __nv_bfloat16* sA1 = xb + (size_t)(m0 + r1) * HDIM + cg0 * 8;
    const __nv_bfloat16* sB0 = wb + (size_t)(n0 + r0) * HDIM + cg0 * 8;
    const __nv_bfloat16* sB1 = wb + (size_t)(n0 + r1) * HDIM + cg0 * 8;

    // ldmatrix lane addresses
    const int arow = lane & 15;
    const uint32_t a_off = ((wm * 64 + arow) * G1_ROWW + ((lane >> 4) << 2)) * 4;
    const int brow = (lane & 7) | ((lane >> 4) << 3);
    const uint32_t b_off = ((wn * 32 + brow) * G1_ROWW + (((lane >> 3) & 1) << 2)) * 4;

    float c[4][4][4];
    #pragma unroll
    for (int i = 0; i < 4; i++)
        #pragma unroll
        for (int j = 0; j < 4; j++)
            #pragma unroll
            for (int r = 0; r < 4; r++) c[i][j][r] = 0.f;

    auto issue = [&](int kt) {
        const uint32_t so = (uint32_t)(kt % 3) * (G1_BUFW * 4);
        const int k0 = kt * 32;
        CP16(As_sm + so + dA0, sA0 + k0);
        CP16(As_sm + so + dA1, sA1 + k0);
        CP16(Bs_sm + so + dA0, sB0 + k0);
        CP16(Bs_sm + so + dA1, sB1 + k0);
    };
    issue(0); CP_COMMIT();
    issue(1); CP_COMMIT();

    for (int kt = 0; kt < 32; kt++) {
        CP_WAIT1();
        __syncthreads();
        if (kt + 2 < 32) issue(kt + 2);
        CP_COMMIT();

        const uint32_t bufoff = (uint32_t)(kt % 3) * (G1_BUFW * 4);
        #pragma unroll
        for (int kk = 0; kk < 2; kk++) {
            unsigned af[4][4], bf[4][2];
            #pragma unroll
            for (int mt = 0; mt < 4; mt++)
                ldsm_x4(af[mt][0], af[mt][1], af[mt][2], af[mt][3],
                        As_sm + bufoff + a_off + mt * (16 * G1_ROWW * 4) + kk * 32);
            ldsm_x4(bf[0][0], bf[0][1], bf[1][0], bf[1][1],
                    Bs_sm + bufoff + b_off + kk * 32);
            ldsm_x4(bf[2][0], bf[2][1], bf[3][0], bf[3][1],
                    Bs_sm + bufoff + b_off + 16 * G1_ROWW * 4 + kk * 32);
            #pragma unroll
            for (int mt = 0; mt < 4; mt++)
                #pragma unroll
                for (int nt = 0; nt < 4; nt++)
                    mma_bf16(c[mt][nt], af[mt], bf[nt]);
        }
    }

    // ---- epilogue: sigmoid(y)*tanh(cells) -> fp16 s_t ----
    #pragma unroll
    for (int mt = 0; mt < 4; mt++) {
        #pragma unroll
        for (int nt = 0; nt < 4; nt++) {
            const int m = m0 + wm * 64 + mt * 16 + grp;
            const int n = n0 + wn * 32 + nt * 8 + qid * 2;
            #pragma unroll
            for (int half = 0; half < 2; half++) {
                const int mm = m + half * 8;
                const float y0 = c[mt][nt][half * 2 + 0];
                const float y1 = c[mt][nt][half * 2 + 1];
                const size_t idx = (size_t)mm * HDIM + n;
                const float2 cl = *(const float2*)(cells + idx);
                const float gate0 = 0.5f + 0.5f * tanh_fast(0.5f * y0);
                const float gate1 = 0.5f + 0.5f * tanh_fast(0.5f * y1);
                const float s0 = gate0 * tanh_fast(cl.x);
                const float s1 = gate1 * tanh_fast(cl.y);
                *(unsigned*)(&g_st[idx]) = pack_f16(s0, s1);
            }
        }
    }
}

// ================= thin tf32 GEMM (g / cv), 4-stage cp.async =================
// Raw fp32 bits fed to tf32 mma (truncation rounding).
#define T_ROWW 20                    // words per row (16 data + 4 pad)
#define T_STGW ((128 + 64) * T_ROWW) // 3840 words per stage
#define T_SMEM (4 * T_STGW * 4)      // 61440 bytes

__device__ __forceinline__ void mma_tf32(float c[4],
        unsigned a0, unsigned a1, unsigned a2, unsigned a3,
        unsigned b0, unsigned b1){
    asm volatile(
        "mma.sync.aligned.m16n8k8.row.col.f32.tf32.tf32.f32 "
        "{%0,%1,%2,%3}, {%4,%5,%6,%7}, {%8,%9}, {%0,%1,%2,%3};\n"
        : "+f"(c[0]), "+f"(c[1]), "+f"(c[2]), "+f"(c[3])
        : "r"(a0), "r"(a1), "r"(a2), "r"(a3), "r"(b0), "r"(b1));
}

__global__ void __launch_bounds__(256, 2)
thin32_kernel(const float* __restrict__ A, const float* __restrict__ Bm,
              float* __restrict__ out, int Mreal, int Nreal, int ldout,
              long long pstride)
{
    extern __shared__ __align__(16) float ts[];

    const int kper = HDIM / gridDim.z;
    const int kb = blockIdx.z * kper;
    const int iters = kper / 16;
    out += (long long)blockIdx.z * pstride;

    const int tid  = threadIdx.x;
    const int lane = tid & 31;
    const int warp = tid >> 5;
    const int grp  = lane >> 2;
    const int qid  = lane & 3;
    const int wm   = warp >> 1;     // 0..3
    const int wn   = warp & 1;      // 0..1
    const int m0 = blockIdx.y * 128;
    const int n0 = 0;               // gridDim.x == 1

    // chunk mapping: A 512 chunks (2/thr), B 256 chunks (1/thr)
    const int ar0 = tid >> 2, acg = tid & 3;
    const int ar1 = ar0 + 64;
    const int brr = tid >> 2;

    const uint32_t sbase = smem_u32(ts);
    const uint32_t dA0 = (ar0 * T_ROWW + acg * 4) * 4;
    const uint32_t dA1 = (ar1 * T_ROWW + acg * 4) * 4;
    const uint32_t dB  = ((128 + brr) * T_ROWW + acg * 4) * 4;

    const int mA0 = m0 + ar0, mA1 = m0 + ar1;
    const unsigned szA0 = (mA0 < Mreal) ? 16u : 0u;
    const unsigned szA1 = (mA1 < Mreal) ? 16u : 0u;
    const unsigned szB  = (n0 + brr < Nreal) ? 16u : 0u;
    const float* sA0 = A + (size_t)(szA0 ? mA0 : 0) * HDIM + kb + acg * 4;
    const float* sA1 = A + (size_t)(szA1 ? mA1 : 0) * HDIM + kb + acg * 4;
    const float* sB  = Bm + (size_t)(szB ? (n0 + brr) : 0) * HDIM + kb + acg * 4;

    float c[2][4][4];
    #pragma unroll
    for (int i = 0; i < 2; i++)
        #pragma unroll
        for (int j = 0; j < 4; j++)
            #pragma unroll
            for (int r = 0; r < 4; r++) c[i][j][r] = 0.f;

    auto issue = [&](int kt) {
        const uint32_t so = (uint32_t)(kt & 3) * (T_STGW * 4);
        const int k0 = kt * 16;
        CP16P(sbase + so + dA0, sA0 + k0, szA0);
        CP16P(sbase + so + dA1, sA1 + k0, szA1);
        CP16P(sbase + so + dB,  sB  + k0, szB);
    };
    issue(0); CP_COMMIT();
    issue(1); CP_COMMIT();
    issue(2); CP_COMMIT();

    for (int kt = 0; kt < iters; kt++) {
        CP_WAIT2();
        __syncthreads();
        if (kt + 3 < iters) issue(kt + 3);
        CP_COMMIT();

        const float* Ac = ts + (size_t)(kt & 3) * T_STGW;
        const float* Bc = Ac + 128 * T_ROWW;
        #pragma unroll
        for (int kk = 0; kk < 2; kk++) {
            unsigned a[2][4], b[4][2];
            #pragma unroll
            for (int mt = 0; mt < 2; mt++) {
                int rb = wm * 32 + mt * 16 + grp;
                a[mt][0] = __float_as_uint(Ac[ rb      * T_ROWW + kk * 8 + qid    ]);
                a[mt][1] = __float_as_uint(Ac[(rb + 8) * T_ROWW + kk * 8 + qid    ]);
                a[mt][2] = __float_as_uint(Ac[ rb      * T_ROWW + kk * 8 + qid + 4]);
                a[mt][3] = __float_as_uint(Ac[(rb + 8) * T_ROWW + kk * 8 + qid + 4]);
            }
            #pragma unroll
            for (int nt = 0; nt < 4; nt++) {
                int nb = wn * 32 + nt * 8 + grp;
                b[nt][0] = __float_as_uint(Bc[nb * T_ROWW + kk * 8 + qid    ]);
                b[nt][1] = __float_as_uint(Bc[nb * T_ROWW + kk * 8 + qid + 4]);
            }
            #pragma unroll
            for (int mt = 0; mt < 2; mt++)
                #pragma unroll
                for (int nt = 0; nt < 4; nt++)
                    mma_tf32(c[mt][nt], a[mt][0], a[mt][1], a[mt][2], a[mt][3],
                             b[nt][0], b[nt][1]);
        }
    }

    #pragma unroll
    for (int mt = 0; mt < 2; mt++) {
        #pragma unroll
        for (int nt = 0; nt < 4; nt++) {
            int m = m0 + wm * 32 + mt * 16 + grp;
            int n = n0 + wn * 32 + nt * 8 + qid * 2;
            #pragma unroll
            for (int halfm = 0; halfm < 2; halfm++) {
                int mm = m + halfm * 8;
                float v0 = c[mt][nt][halfm * 2 + 0];
                float v1 = c[mt][nt][halfm * 2 + 1];
                if (mm < Mreal) {
                    size_t row = (size_t)mm * ldout;
                    if (n     < Nreal) out[row + n    ] = v0;
                    if (n + 1 < Nreal) out[row + n + 1] = v1;
                }
            }
        }
    }
}

// ================= cs: fp16 m16n8k16 thin GEMM, 4-stage cp.async =============
// A = s_t fp16 [32768][1024], B = g_wsh (fp16, padded 64 rows). BK=32 halves.
__device__ __forceinline__ void mma_f16(float c[4], const unsigned a[4],
                                        const unsigned b[2]){
    asm volatile(
        "mma.sync.aligned.m16n8k16.row.col.f32.f16.f16.f32 "
        "{%0,%1,%2,%3}, {%4,%5,%6,%7}, {%8,%9}, {%0,%1,%2,%3};\n"
        : "+f"(c[0]), "+f"(c[1]), "+f"(c[2]), "+f"(c[3])
        : "r"(a[0]), "r"(a[1]), "r"(a[2]), "r"(a[3]), "r"(b[0]), "r"(b[1]));
}

__global__ void __launch_bounds__(256, 2)
thin16_kernel(float* __restrict__ out)
{
    extern __shared__ __align__(16) __half hs[];
    // rows of 40 halves (32 data + 8 pad) = 80 bytes; A 128 rows, B 64 rows
    // stage = 192*80 = 15360 B; 4 stages

    const int tid  = threadIdx.x;
    const int lane = tid & 31;
    const int warp = tid >> 5;
    const int grp  = lane >> 2;
    const int qid  = lane & 3;
    const int wm   = warp >> 1;     // 0..3
    const int wn   = warp & 1;      // 0..1
    const int m0 = blockIdx.y * 128;

    const int ar0 = tid >> 2, acg = tid & 3;
    const int ar1 = ar0 + 64;
    const int brr = tid >> 2;

    const __half* __restrict__ Ah = g_st;
    const __half* __restrict__ Bh = g_wsh;

    const uint32_t sbase = smem_u32(hs);
    const uint32_t dA0 = ar0 * 80 + acg * 16;
    const uint32_t dA1 = ar1 * 80 + acg * 16;
    const uint32_t dB  = (128 + brr) * 80 + acg * 16;
    const __half* sA0 = Ah + (size_t)(m0 + ar0) * HDIM + acg * 8;
    const __half* sA1 = Ah + (size_t)(m0 + ar1) * HDIM + acg * 8;
    const __half* sB  = Bh + (size_t)brr * HDIM + acg * 8;

    // ldmatrix lane addresses (bytes within stage)
    const uint32_t a_off = (uint32_t)(wm * 32 + (lane & 15)) * 80 + ((lane >> 4) << 4);
    const int brow = (lane & 7) | ((lane >> 4) << 3);
    const uint32_t b_off = (uint32_t)(128 + wn * 32 + brow) * 80 + (((lane >> 3) & 1) << 4);

    float c[2][4][4];
    #pragma unroll
    for (int i = 0; i < 2; i++)
        #pragma unroll
        for (int j = 0; j < 4; j++)
            #pragma unroll
            for (int r = 0; r < 4; r++) c[i][j][r] = 0.f;

    auto issue = [&](int kt) {
        const uint32_t so = (uint32_t)(kt & 3) * 15360u;
        const int k0 = kt * 32;
        CP16(sbase + so + dA0, sA0 + k0);
        CP16(sbase + so + dA1, sA1 + k0);
        CP16(sbase + so + dB,  sB  + k0);
    };
    issue(0); CP_COMMIT();
    issue(1); CP_COMMIT();
    issue(2); CP_COMMIT();

    for (int kt = 0; kt < 32; kt++) {
        CP_WAIT2();
        __syncthreads();
        if (kt + 3 < 32) issue(kt + 3);
        CP_COMMIT();

        const uint32_t st = sbase + (uint32_t)(kt & 3) * 15360u;
        #pragma unroll
        for (int kk = 0; kk < 2; kk++) {
            unsigned af[2][4], bf[4][2];
            #pragma unroll
            for (int mt = 0; mt < 2; mt++)
                ldsm_x4(af[mt][0], af[mt][1], af[mt][2], af[mt][3],
                        st + a_off + mt * (16 * 80) + kk * 32);
            ldsm_x4(bf[0][0], bf[0][1], bf[1][0], bf[1][1],
                    st + b_off + kk * 32);
            ldsm_x4(bf[2][0], bf[2][1], bf[3][0], bf[3][1],
                    st + b_off + 16 * 80 + kk * 32);
            #pragma unroll
            for (int mt = 0; mt < 2; mt++)
                #pragma unroll
                for (int nt = 0; nt < 4; nt++)
                    mma_f16(c[mt][nt], af[mt], bf[nt]);
        }
    }

    #pragma unroll
    for (int mt = 0; mt < 2; mt++) {
        #pragma unroll
        for (int nt = 0; nt < 4; nt++) {
            int m = m0 + wm * 32 + mt * 16 + grp;
            int n = wn * 32 + nt * 8 + qid * 2;
            #pragma unroll
            for (int halfm = 0; halfm < 2; halfm++) {
                int mm = m + halfm * 8;
                size_t row = (size_t)mm * 64;
                out[row + n    ] = c[mt][nt][halfm * 2 + 0];
                out[row + n + 1] = c[mt][nt][halfm * 2 + 1];
            }
        }
    }
}

// ---------------- attention logits: block per (b, 64-t chunk) ----------------
#define ATC 64
__global__ void __launch_bounds__(256)
attn_logits_kernel(const float* __restrict__ Wh)
{
    const int b  = blockIdx.y;
    const int t0 = blockIdx.x * ATC;
    const int tid = threadIdx.x;

    __shared__ float cvsh[KQ * KQ];        // [k][j], summed partials
    __shared__ float whsh[KQ];
    __shared__ float gsh[ATC][KQ + 1];
    __shared__ float cssh[ATC][KQ + 1];
    __shared__ float zsh[ATC][51];
    __shared__ float inv_s[ATC];

    for (int i = tid; i < KQ * KQ; i += 256) {
        int k = i / KQ, j = i - k * KQ;
        size_t base = (size_t)(b * KQ + k) * 64 + j;
        cvsh[i] = g_cv[base] + g_cv[base + CV_SLICE]
                + g_cv[base + 2 * CV_SLICE] + g_cv[base + 3 * CV_SLICE];
    }
    if (tid < KQ) whsh[tid] = Wh[tid];
    for (int i = tid; i < ATC * KQ; i += 256) {
        int t = i / KQ, j = i - t * KQ;
        size_t base = (size_t)(b * TDIM + t0 + t) * 64 + j;
        gsh[t][j]  = g_g [base];
        cssh[t][j] = g_cs[base];
    }
    __syncthreads();

    // 64*50 dot-products of length 49
    for (int idx = tid; idx < ATC * 50; idx += 256) {
        const int t = idx / 50, k = idx - t * 50;
        const float* row = (k < 49) ? &cvsh[k * KQ] : &cssh[t][0];
        const float* gr  = &gsh[t][0];
        float acc = 0.f;
        #pragma unroll 7
        for (int j = 0; j < KQ; j++)
            acc += tanh_fast(row[j] + gr[j]) * whsh[j];
        zsh[t][k] = acc;
    }
    __syncthreads();

    // per-t softmax (alpha over 49, beta from extended 50)
    if (tid < ATC) {
        const int t = tid;
        float mx = -1e30f;
        #pragma unroll 7
        for (int j = 0; j < KQ; j++) mx = fmaxf(mx, zsh[t][j]);
        float s = 0.f;
        #pragma unroll 7
        for (int j = 0; j < KQ; j++) {
            float e = __expf(zsh[t][j] - mx);
            zsh[t][j] = e; s += e;
        }
        inv_s[t] = 1.f / s;
        const float zx = zsh[t][49];
        const float M2 = fmaxf(mx, zx);
        const float denom = __expf(mx - M2) * s + __expf(zx - M2);
        g_be[b * TDIM + t0 + t] = __expf(zx - M2) / denom;
    }
    __syncthreads();

    // coalesced alpha writeback
    for (int i = tid; i < ATC * KQ; i += 256) {
        int t = i / KQ, j = i - t * KQ;
        g_al[(size_t)(b * TDIM + t0 + t) * 64 + j] = zsh[t][j] * inv_s[t];
    }
}

// ---------------- final: out = beta*s_t + (1-beta)*(alpha@V) + hiddens ------
__global__ void __launch_bounds__(256)
final_kernel(const float* __restrict__ V, const float* __restrict__ hiddens,
             float* __restrict__ out)
{
    const int b  = blockIdx.z;
    const int t0 = blockIdx.y * 16;
    const int h0 = blockIdx.x * 256;
    const int tid  = threadIdx.x;
    const int hthr = tid & 63;
    const int tthr = tid >> 6;

    __shared__ float al[16][52];
    __shared__ float be[16];

    for (int i = tid; i < 16 * KQ; i += 256) {
        int tt = i / KQ, k = i - tt * KQ;
        al[tt][k] = g_al[(size_t)(b * TDIM + t0 + tt) * 64 + k];
    }
    if (tid < 16) be[tid] = g_be[b * TDIM + t0 + tid];
    __syncthreads();

    const int h = h0 + hthr * 4;
    float4 acc[4];
    #pragma unroll
    for (int i = 0; i < 4; i++) acc[i] = make_float4(0.f, 0.f, 0.f, 0.f);

    const float* Vb = V + (size_t)b * KQ * HDIM + h;
    for (int k = 0; k < KQ; k++) {
        float4 v = *(const float4*)(Vb + (size_t)k * HDIM);
        #pragma unroll
        for (int i = 0; i < 4; i++) {
            float a = al[tthr * 4 + i][k];
            acc[i].x += a * v.x; acc[i].y += a * v.y;
            acc[i].z += a * v.z; acc[i].w += a * v.w;
        }
    }
    #pragma unroll
    for (int i = 0; i < 4; i++) {
        int t = t0 + tthr * 4 + i;
        size_t idx = ((size_t)(b * TDIM + t)) * HDIM + h;
        uint2 su = *(const uint2*)(g_st + idx);       // 4 fp16
        float2 s01 = __half22float2(*(__half2*)&su.x);
        float2 s23 = __half22float2(*(__half2*)&su.y);
        float4 hd = *(const float4*)(hiddens + idx);
        float bt = be[tthr * 4 + i];
        float om = 1.f - bt;
        float4 o;
        o.x = bt * s01.x + om * acc[i].x + hd.x;
        o.y = bt * s01.y + om * acc[i].y + hd.y;
        o.z = bt * s23.x + om * acc[i].z + hd.z;
        o.w = bt * s23.y + om * acc[i].w + hd.w;
        *(float4*)(out + idx) = o;
    }
}

// ---------------- launch ----------------
extern "C" void kernel_launch(void* const* d_in, const int* in_sizes, int n_in,
                              void* d_out, int out_size)
{
    const float* x       = (const float*)d_in[0];
    const float* hiddens = (const float*)d_in[1];
    const float* cells   = (const float*)d_in[2];
    const float* V       = (const float*)d_in[3];
    const float* Wx      = (const float*)d_in[4];
    // d_in[5] = Whh, unused: h_prev == 0 so its contribution is exactly zero.
    const float* Wv      = (const float*)d_in[6];
    const float* Wg      = (const float*)d_in[7];
    const float* Ws      = (const float*)d_in[8];
    const float* Wh      = (const float*)d_in[9];
    float* out = (float*)d_out;

    __nv_bfloat16 *p_xb, *p_wb; __half* p_wsh;
    float *p_g, *p_cs, *p_cv;
    cudaGetSymbolAddress((void**)&p_xb, g_xb);
    cudaGetSymbolAddress((void**)&p_wb, g_wb);
    cudaGetSymbolAddress((void**)&p_wsh, g_wsh);
    cudaGetSymbolAddress((void**)&p_g,  g_g);
    cudaGetSymbolAddress((void**)&p_cs, g_cs);
    cudaGetSymbolAddress((void**)&p_cv, g_cv);

    cudaFuncSetAttribute(gemm1_bf16_kernel,
                         cudaFuncAttributeMaxDynamicSharedMemorySize, G1_SMEM);
    cudaFuncSetAttribute(thin32_kernel,
                         cudaFuncAttributeMaxDynamicSharedMemorySize, T_SMEM);
    cudaFuncSetAttribute(thin16_kernel,
                         cudaFuncAttributeMaxDynamicSharedMemorySize, T_SMEM);

    // x, Wx -> bf16; Ws -> fp16 (padded)
    cvt_bf16_kernel<<<(MT_ROWS * HDIM / 4 + 255) / 256, 256>>>(x, p_xb,
                                                               MT_ROWS * HDIM / 4);
    cvt_bf16_kernel<<<(HDIM * HDIM / 4 + 255) / 256, 256>>>(Wx, p_wb,
                                                            HDIM * HDIM / 4);
    cvt_ws_kernel<<<256, 256>>>(Ws, p_wsh);

    // s_t = sigmoid(x @ Wx^T) * tanh(cells)  [32768 x 1024], bf16 HMMA
    gemm1_bf16_kernel<<<dim3(8, 256), 256, G1_SMEM>>>(cells);
    // g = hiddens @ Wg^T                     [32768 x 49]
    thin32_kernel<<<dim3(1, 256, 1), 256, T_SMEM>>>(hiddens, Wg, p_g,
                                                    MT_ROWS, KQ, 64, 0);
    // cs = s_t @ Ws^T                        [32768 x 49]  (fp16 HMMA)
    thin16_kernel<<<dim3(1, 256, 1), 256, T_SMEM>>>(p_cs);
    // cv = V @ Wv^T  (V as [3136, 1024]), K-split x4 into partial slices
    thin32_kernel<<<dim3(1, 25, 4), 256, T_SMEM>>>(V, Wv, p_cv,
                                                   3136, KQ, 64, CV_SLICE);
    // alpha / beta per (b, 64-t chunk)
    attn_logits_kernel<<<dim3(TDIM / ATC, BDIM), 256>>>(Wh);
    // out = beta*s_t + (1-beta)*(alpha@V) + hiddens
    final_kernel<<<dim3(4, 32, 64), 256>>>(V, hiddens, out);
}

// round 17
// speedup vs baseline: 2.5706x; 1.0239x over previous
#include <cuda_runtime.h>
#include <cuda_fp16.h>
#include <cuda_bf16.h>
#include <math.h>
#include <stdint.h>

// Problem dims (fixed by the reference)
#define BDIM 64
#define TDIM 512
#define HDIM 1024
#define KQ   49
#define MT_ROWS (BDIM*TDIM)   // 32768

// ---------------- static scratch (no allocs allowed) ----------------
__device__ __half g_st[33554432];              // s_t  [B*T, H] fp16 (64 MB)
__device__ __nv_bfloat16 g_xb[33554432];       // x in bf16      (64 MB)
__device__ __nv_bfloat16 g_wb[HDIM * HDIM];    // Wx in bf16     (2 MB)
__device__ __half g_wsh[64 * HDIM];            // Ws fp16, zero-padded to 64 rows
__device__ float g_g [MT_ROWS * 64];           // g   [B*T, 49] padded to 64
__device__ float g_cs[MT_ROWS * 64];           // content_s raw (s_t@Ws^T)
__device__ float g_cv[4 * 3200 * 64];          // cv partials (4 K-slices)
__device__ float g_al[MT_ROWS * 64];           // alpha [B*T, 49] padded
__device__ float g_be[MT_ROWS];                // beta  [B*T]

#define CV_SLICE (3200 * 64)

// ---------------- helpers ----------------
__device__ __forceinline__ float tanh_fast(float x){
    float y; asm("tanh.approx.f32 %0, %1;" : "=f"(y) : "f"(x)); return y;
}
__device__ __forceinline__ unsigned h2tanh(unsigned x){
    unsigned y; asm("tanh.approx.f16x2 %0, %1;" : "=r"(y) : "r"(x)); return y;
}
__device__ __forceinline__ unsigned pack_f16(float lo, float hi){
    unsigned r; asm("cvt.rn.f16x2.f32 %0, %1, %2;" : "=r"(r) : "f"(hi), "f"(lo)); return r;
}
__device__ __forceinline__ unsigned pack_bf16(float lo, float hi){
    unsigned r; asm("cvt.rn.bf16x2.f32 %0, %1, %2;" : "=r"(r) : "f"(hi), "f"(lo)); return r;
}
__device__ __forceinline__ uint32_t smem_u32(const void* p) {
    uint32_t a;
    asm("{ .reg .u64 t; cvta.to.shared.u64 t, %1; cvt.u32.u64 %0, t; }"
        : "=r"(a) : "l"(p));
    return a;
}
__device__ __forceinline__ void ldsm_x4(unsigned &r0, unsigned &r1,
                                        unsigned &r2, unsigned &r3, uint32_t addr){
    asm volatile("ldmatrix.sync.aligned.m8n8.x4.shared.b16 {%0,%1,%2,%3}, [%4];"
        : "=r"(r0), "=r"(r1), "=r"(r2), "=r"(r3) : "r"(addr));
}
#define CP16(dst, src) \
    asm volatile("cp.async.cg.shared.global [%0], [%1], 16;" :: "r"(dst), "l"(src))
#define CP16P(dst, src, sz) \
    asm volatile("cp.async.cg.shared.global [%0], [%1], 16, %2;" :: "r"(dst), "l"(src), "r"(sz))
#define CP_COMMIT() asm volatile("cp.async.commit_group;" ::: "memory")
#define CP_WAIT2()  asm volatile("cp.async.wait_group 2;" ::: "memory")

// ---------------- fp32 -> bf16 conversion pass ----------------
__global__ void __launch_bounds__(256)
cvt_bf16_kernel(const float* __restrict__ src, __nv_bfloat16* __restrict__ dst,
                int n4)
{
    int i = blockIdx.x * 256 + threadIdx.x;
    if (i < n4) {
        float4 v = ((const float4*)src)[i];
        uint2 p;
        p.x = pack_bf16(v.x, v.y);
        p.y = pack_bf16(v.z, v.w);
        ((uint2*)dst)[i] = p;
    }
}

// Ws (49x1024 fp32) -> fp16, zero-padded to 64 rows
__global__ void __launch_bounds__(256)
cvt_ws_kernel(const float* __restrict__ Ws, __half* __restrict__ dst)
{
    int i = blockIdx.x * 256 + threadIdx.x;   // 65536
    int row = i >> 10;
    float v = (row < KQ) ? Ws[i] : 0.f;
    dst[i] = __float2half(v);
}

// ================= GEMM1: bf16 mma.sync m16n8k16, 4-stage cp.async =========
#define G1_ROWW 20                 // words per smem row (32 bf16 = 16 words + pad)
#define G1_BUFW (128 * G1_ROWW)    // 2560 words per matrix per stage
#define G1_SMEM (8 * G1_BUFW * 4)  // 81920 bytes (4 stages x A,B)

__device__ __forceinline__ void mma_bf16(float c[4], const unsigned a[4],
                                         const unsigned b[2]){
    asm volatile(
        "mma.sync.aligned.m16n8k16.row.col.f32.bf16.bf16.f32 "
        "{%0,%1,%2,%3}, {%4,%5,%6,%7}, {%8,%9}, {%0,%1,%2,%3};\n"
        : "+f"(c[0]), "+f"(c[1]), "+f"(c[2]), "+f"(c[3])
        : "r"(a[0]), "r"(a[1]), "r"(a[2]), "r"(a[3]), "r"(b[0]), "r"(b[1]));
}

__global__ void __launch_bounds__(256, 2)
gemm1_bf16_kernel(const float* __restrict__ cells)
{
    extern __shared__ __align__(16) unsigned g1s[];
    unsigned* Asm = g1s;                 // 4 stages x G1_BUFW
    unsigned* Bsm = g1s + 4 * G1_BUFW;

    const int tid  = threadIdx.x;
    const int lane = tid & 31;
    const int warp = tid >> 5;
    const int grp  = lane >> 2;     // 0..7
    const int qid  = lane & 3;      // 0..3
    const int wm   = warp >> 2;     // 0..1
    const int wn   = warp & 3;      // 0..3

    const int m0 = blockIdx.y * 128;
    const int n0 = blockIdx.x * 128;

    // 512 chunks (128 rows x 4 chunks of 8 bf16) per matrix, 2 per thread
    const int r0 = tid >> 2,         cg0 = tid & 3;
    const int r1 = (tid + 256) >> 2;

    const __nv_bfloat16* __restrict__ xb = g_xb;
    const __nv_bfloat16* __restrict__ wb = g_wb;

    const uint32_t As_sm = smem_u32(Asm);
    const uint32_t Bs_sm = smem_u32(Bsm);
    const uint32_t dA0 = (r0 * G1_ROWW + cg0 * 4) * 4;
    const uint32_t dA1 = (r1 * G1_ROWW + cg0 * 4) * 4;
    const __nv_bfloat16* sA0 = xb + (size_t)(m0 + r0) * HDIM + cg0 * 8;
    const __nv_bfloat16* sA1 = xb + (size_t)(m0 + r1) * HDIM + cg0 * 8;
    const __nv_bfloat16* sB0 = wb + (size_t)(n0 + r0) * HDIM + cg0 * 8;
    const __nv_bfloat16* sB1 = wb + (size_t)(n0 + r1) * HDIM + cg0 * 8;

    // ldmatrix lane addresses
    const int arow = lane & 15;
    const uint32_t a_off = ((wm * 64 + arow) * G1_ROWW + ((lane >> 4) << 2)) * 4;
    const int brow = (lane & 7) | ((lane >> 4) << 3);
    const uint32_t b_off = ((wn * 32 + brow) * G1_ROWW + (((lane >> 3) & 1) << 2)) * 4;

    float c[4][4][4];
    #pragma unroll
    for (int i = 0; i < 4; i++)
        #pragma unroll
        for (int j = 0; j < 4; j++)
            #pragma unroll
            for (int r = 0; r < 4; r++) c[i][j][r] = 0.f;

    auto issue = [&](int kt) {
        const uint32_t so = (uint32_t)(kt & 3) * (G1_BUFW * 4);
        const int k0 = kt * 32;
        CP16(As_sm + so + dA0, sA0 + k0);
        CP16(As_sm + so + dA1, sA1 + k0);
        CP16(Bs_sm + so + dA0, sB0 + k0);
        CP16(Bs_sm + so + dA1, sB1 + k0);
    };
    issue(0); CP_COMMIT();
    issue(1); CP_COMMIT();
    issue(2); CP_COMMIT();

    for (int kt = 0; kt < 32; kt++) {
        CP_WAIT2();
        __syncthreads();
        if (kt + 3 < 32) issue(kt + 3);
        CP_COMMIT();

        const uint32_t bufoff = (uint32_t)(kt & 3) * (G1_BUFW * 4);
        // load fragments for BOTH k-halves up front (frag double buffer),
        // then run all MMAs — lets ptxas hide LDSM latency under HMMA.
        unsigned af[2][4][4], bf[2][4][2];
        #pragma unroll
        for (int kk = 0; kk < 2; kk++) {
            #pragma unroll
            for (int mt = 0; mt < 4; mt++)
                ldsm_x4(af[kk][mt][0], af[kk][mt][1], af[kk][mt][2], af[kk][mt][3],
                        As_sm + bufoff + a_off + mt * (16 * G1_ROWW * 4) + kk * 32);
            ldsm_x4(bf[kk][0][0], bf[kk][0][1], bf[kk][1][0], bf[kk][1][1],
                    Bs_sm + bufoff + b_off + kk * 32);
            ldsm_x4(bf[kk][2][0], bf[kk][2][1], bf[kk][3][0], bf[kk][3][1],
                    Bs_sm + bufoff + b_off + 16 * G1_ROWW * 4 + kk * 32);
        }
        #pragma unroll
        for (int kk = 0; kk < 2; kk++)
            #pragma unroll
            for (int mt = 0; mt < 4; mt++)
                #pragma unroll
                for (int nt = 0; nt < 4; nt++)
                    mma_bf16(c[mt][nt], af[kk][mt], bf[kk][nt]);
    }

    // ---- epilogue: sigmoid(y)*tanh(cells) -> fp16 s_t ----
    #pragma unroll
    for (int mt = 0; mt < 4; mt++) {
        #pragma unroll
        for (int nt = 0; nt < 4; nt++) {
            const int m = m0 + wm * 64 + mt * 16 + grp;
            const int n = n0 + wn * 32 + nt * 8 + qid * 2;
            #pragma unroll
            for (int half = 0; half < 2; half++) {
                const int mm = m + half * 8;
                const float y0 = c[mt][nt][half * 2 + 0];
                const float y1 = c[mt][nt][half * 2 + 1];
                const size_t idx = (size_t)mm * HDIM + n;
                const float2 cl = *(const float2*)(cells + idx);
                const float gate0 = 0.5f + 0.5f * tanh_fast(0.5f * y0);
                const float gate1 = 0.5f + 0.5f * tanh_fast(0.5f * y1);
                const float s0 = gate0 * tanh_fast(cl.x);
                const float s1 = gate1 * tanh_fast(cl.y);
                *(unsigned*)(&g_st[idx]) = pack_f16(s0, s1);
            }
        }
    }
}

// ================= thin tf32 GEMM (g / cv), 4-stage cp.async =================
#define T_ROWW 20                    // words per row (16 data + 4 pad)
#define T_STGW ((128 + 64) * T_ROWW) // 3840 words per stage
#define T_SMEM (4 * T_STGW * 4)      // 61440 bytes

__device__ __forceinline__ void mma_tf32(float c[4],
        unsigned a0, unsigned a1, unsigned a2, unsigned a3,
        unsigned b0, unsigned b1){
    asm volatile(
        "mma.sync.aligned.m16n8k8.row.col.f32.tf32.tf32.f32 "
        "{%0,%1,%2,%3}, {%4,%5,%6,%7}, {%8,%9}, {%0,%1,%2,%3};\n"
        : "+f"(c[0]), "+f"(c[1]), "+f"(c[2]), "+f"(c[3])
        : "r"(a0), "r"(a1), "r"(a2), "r"(a3), "r"(b0), "r"(b1));
}

__global__ void __launch_bounds__(256, 2)
thin32_kernel(const float* __restrict__ A, const float* __restrict__ Bm,
              float* __restrict__ out, int Mreal, int Nreal, int ldout,
              long long pstride)
{
    extern __shared__ __align__(16) float ts[];

    const int kper = HDIM / gridDim.z;
    const int kb = blockIdx.z * kper;
    const int iters = kper / 16;
    out += (long long)blockIdx.z * pstride;

    const int tid  = threadIdx.x;
    const int lane = tid & 31;
    const int warp = tid >> 5;
    const int grp  = lane >> 2;
    const int qid  = lane & 3;
    const int wm   = warp >> 1;     // 0..3
    const int wn   = warp & 1;      // 0..1
    const int m0 = blockIdx.y * 128;
    const int n0 = 0;

    const int ar0 = tid >> 2, acg = tid & 3;
    const int ar1 = ar0 + 64;
    const int brr = tid >> 2;

    const uint32_t sbase = smem_u32(ts);
    const uint32_t dA0 = (ar0 * T_ROWW + acg * 4) * 4;
    const uint32_t dA1 = (ar1 * T_ROWW + acg * 4) * 4;
    const uint32_t dB  = ((128 + brr) * T_ROWW + acg * 4) * 4;

    const int mA0 = m0 + ar0, mA1 = m0 + ar1;
    const unsigned szA0 = (mA0 < Mreal) ? 16u : 0u;
    const unsigned szA1 = (mA1 < Mreal) ? 16u : 0u;
    const unsigned szB  = (n0 + brr < Nreal) ? 16u : 0u;
    const float* sA0 = A + (size_t)(szA0 ? mA0 : 0) * HDIM + kb + acg * 4;
    const float* sA1 = A + (size_t)(szA1 ? mA1 : 0) * HDIM + kb + acg * 4;
    const float* sB  = Bm + (size_t)(szB ? (n0 + brr) : 0) * HDIM + kb + acg * 4;

    float c[2][4][4];
    #pragma unroll
    for (int i = 0; i < 2; i++)
        #pragma unroll
        for (int j = 0; j < 4; j++)
            #pragma unroll
            for (int r = 0; r < 4; r++) c[i][j][r] = 0.f;

    auto issue = [&](int kt) {
        const uint32_t so = (uint32_t)(kt & 3) * (T_STGW * 4);
        const int k0 = kt * 16;
        CP16P(sbase + so + dA0, sA0 + k0, szA0);
        CP16P(sbase + so + dA1, sA1 + k0, szA1);
        CP16P(sbase + so + dB,  sB  + k0, szB);
    };
    issue(0); CP_COMMIT();
    issue(1); CP_COMMIT();
    issue(2); CP_COMMIT();

    for (int kt = 0; kt < iters; kt++) {
        CP_WAIT2();
        __syncthreads();
        if (kt + 3 < iters) issue(kt + 3);
        CP_COMMIT();

        const float* Ac = ts + (size_t)(kt & 3) * T_STGW;
        const float* Bc = Ac + 128 * T_ROWW;
        #pragma unroll
        for (int kk = 0; kk < 2; kk++) {
            unsigned a[2][4], b[4][2];
            #pragma unroll
            for (int mt = 0; mt < 2; mt++) {
                int rb = wm * 32 + mt * 16 + grp;
                a[mt][0] = __float_as_uint(Ac[ rb      * T_ROWW + kk * 8 + qid    ]);
                a[mt][1] = __float_as_uint(Ac[(rb + 8) * T_ROWW + kk * 8 + qid    ]);
                a[mt][2] = __float_as_uint(Ac[ rb      * T_ROWW + kk * 8 + qid + 4]);
                a[mt][3] = __float_as_uint(Ac[(rb + 8) * T_ROWW + kk * 8 + qid + 4]);
            }
            #pragma unroll
            for (int nt = 0; nt < 4; nt++) {
                int nb = wn * 32 + nt * 8 + grp;
                b[nt][0] = __float_as_uint(Bc[nb * T_ROWW + kk * 8 + qid    ]);
                b[nt][1] = __float_as_uint(Bc[nb * T_ROWW + kk * 8 + qid + 4]);
            }
            #pragma unroll
            for (int mt = 0; mt < 2; mt++)
                #pragma unroll
                for (int nt = 0; nt < 4; nt++)
                    mma_tf32(c[mt][nt], a[mt][0], a[mt][1], a[mt][2], a[mt][3],
                             b[nt][0], b[nt][1]);
        }
    }

    #pragma unroll
    for (int mt = 0; mt < 2; mt++) {
        #pragma unroll
        for (int nt = 0; nt < 4; nt++) {
            int m = m0 + wm * 32 + mt * 16 + grp;
            int n = n0 + wn * 32 + nt * 8 + qid * 2;
            #pragma unroll
            for (int halfm = 0; halfm < 2; halfm++) {
                int mm = m + halfm * 8;
                float v0 = c[mt][nt][halfm * 2 + 0];
                float v1 = c[mt][nt][halfm * 2 + 1];
                if (mm < Mreal) {
                    size_t row = (size_t)mm * ldout;
                    if (n     < Nreal) out[row + n    ] = v0;
                    if (n + 1 < Nreal) out[row + n + 1] = v1;
                }
            }
        }
    }
}

// ================= cs: fp16 m16n8k16 thin GEMM, 4-stage cp.async =============
__device__ __forceinline__ void mma_f16(float c[4], const unsigned a[4],
                                        const unsigned b[2]){
    asm volatile(
        "mma.sync.aligned.m16n8k16.row.col.f32.f16.f16.f32 "
        "{%0,%1,%2,%3}, {%4,%5,%6,%7}, {%8,%9}, {%0,%1,%2,%3};\n"
        : "+f"(c[0]), "+f"(c[1]), "+f"(c[2]), "+f"(c[3])
        : "r"(a[0]), "r"(a[1]), "r"(a[2]), "r"(a[3]), "r"(b[0]), "r"(b[1]));
}

__global__ void __launch_bounds__(256, 2)
thin16_kernel(float* __restrict__ out)
{
    extern __shared__ __align__(16) __half hs[];
    // rows of 40 halves (32 data + 8 pad) = 80 bytes; A 128 rows, B 64 rows
    // stage = 192*80 = 15360 B; 4 stages

    const int tid  = threadIdx.x;
    const int lane = tid & 31;
    const int warp = tid >> 5;
    const int grp  = lane >> 2;
    const int qid  = lane & 3;
    const int wm   = warp >> 1;     // 0..3
    const int wn   = warp & 1;      // 0..1
    const int m0 = blockIdx.y * 128;

    const int ar0 = tid >> 2, acg = tid & 3;
    const int ar1 = ar0 + 64;
    const int brr = tid >> 2;

    const __half* __restrict__ Ah = g_st;
    const __half* __restrict__ Bh = g_wsh;

    const uint32_t sbase = smem_u32(hs);
    const uint32_t dA0 = ar0 * 80 + acg * 16;
    const uint32_t dA1 = ar1 * 80 + acg * 16;
    const uint32_t dB  = (128 + brr) * 80 + acg * 16;
    const __half* sA0 = Ah + (size_t)(m0 + ar0) * HDIM + acg * 8;
    const __half* sA1 = Ah + (size_t)(m0 + ar1) * HDIM + acg * 8;
    const __half* sB  = Bh + (size_t)brr * HDIM + acg * 8;

    const uint32_t a_off = (uint32_t)(wm * 32 + (lane & 15)) * 80 + ((lane >> 4) << 4);
    const int brow = (lane & 7) | ((lane >> 4) << 3);
    const uint32_t b_off = (uint32_t)(128 + wn * 32 + brow) * 80 + (((lane >> 3) & 1) << 4);

    float c[2][4][4];
    #pragma unroll
    for (int i = 0; i < 2; i++)
        #pragma unroll
        for (int j = 0; j < 4; j++)
            #pragma unroll
            for (int r = 0; r < 4; r++) c[i][j][r] = 0.f;

    auto issue = [&](int kt) {
        const uint32_t so = (uint32_t)(kt & 3) * 15360u;
        const int k0 = kt * 32;
        CP16(sbase + so + dA0, sA0 + k0);
        CP16(sbase + so + dA1, sA1 + k0);
        CP16(sbase + so + dB,  sB  + k0);
    };
    issue(0); CP_COMMIT();
    issue(1); CP_COMMIT();
    issue(2); CP_COMMIT();

    for (int kt = 0; kt < 32; kt++) {
        CP_WAIT2();
        __syncthreads();
        if (kt + 3 < 32) issue(kt + 3);
        CP_COMMIT();

        const uint32_t st = sbase + (uint32_t)(kt & 3) * 15360u;
        unsigned af[2][2][4], bf[2][4][2];
        #pragma unroll
        for (int kk = 0; kk < 2; kk++) {
            #pragma unroll
            for (int mt = 0; mt < 2; mt++)
                ldsm_x4(af[kk][mt][0], af[kk][mt][1], af[kk][mt][2], af[kk][mt][3],
                        st + a_off + mt * (16 * 80) + kk * 32);
            ldsm_x4(bf[kk][0][0], bf[kk][0][1], bf[kk][1][0], bf[kk][1][1],
                    st + b_off + kk * 32);
            ldsm_x4(bf[kk][2][0], bf[kk][2][1], bf[kk][3][0], bf[kk][3][1],
                    st + b_off + 16 * 80 + kk * 32);
        }
        #pragma unroll
        for (int kk = 0; kk < 2; kk++)
            #pragma unroll
            for (int mt = 0; mt < 2; mt++)
                #pragma unroll
                for (int nt = 0; nt < 4; nt++)
                    mma_f16(c[mt][nt], af[kk][mt], bf[kk][nt]);
    }

    #pragma unroll
    for (int mt = 0; mt < 2; mt++) {
        #pragma unroll
        for (int nt = 0; nt < 4; nt++) {
            int m = m0 + wm * 32 + mt * 16 + grp;
            int n = wn * 32 + nt * 8 + qid * 2;
            #pragma unroll
            for (int halfm = 0; halfm < 2; halfm++) {
                int mm = m + halfm * 8;
                size_t row = (size_t)mm * 64;
                out[row + n    ] = c[mt][nt][halfm * 2 + 0];
                out[row + n + 1] = c[mt][nt][halfm * 2 + 1];
            }
        }
    }
}

// ---------------- attention logits: block per (b, 64-t chunk), f16x2 tanh ----
#define ATC 64
#define JP 25            // 25 half2 pairs cover j = 0..49 (j=49 is zero pad)
__global__ void __launch_bounds__(256)
attn_logits_kernel(const float* __restrict__ Wh)
{
    const int b  = blockIdx.y;
    const int t0 = blockIdx.x * ATC;
    const int tid = threadIdx.x;

    __shared__ __half2 cvh[KQ][JP + 1];    // cv rows as half2 pairs
    __shared__ __half2 ghh[ATC][JP + 1];   // g rows
    __shared__ __half2 csh[ATC][JP + 1];   // cs rows
    __shared__ float whsh[2 * JP];         // Wh padded with zeros
    __shared__ float zsh[ATC][51];
    __shared__ float inv_s[ATC];

    // cv: sum 4 K-slice partials, pack to half2
    for (int i = tid; i < KQ * JP; i += 256) {
        int k = i / JP, jp = i - k * JP;
        int j0 = 2 * jp, j1 = j0 + 1;
        size_t base = (size_t)(b * KQ + k) * 64;
        float f0 = g_cv[base + j0] + g_cv[base + j0 + CV_SLICE]
                 + g_cv[base + j0 + 2 * CV_SLICE] + g_cv[base + j0 + 3 * CV_SLICE];
        float f1 = 0.f;
        if (j1 < KQ)
            f1 = g_cv[base + j1] + g_cv[base + j1 + CV_SLICE]
               + g_cv[base + j1 + 2 * CV_SLICE] + g_cv[base + j1 + 3 * CV_SLICE];
        cvh[k][jp] = __floats2half2_rn(f0, f1);
    }
    if (tid < 2 * JP) whsh[tid] = (tid < KQ) ? Wh[tid] : 0.f;
    for (int i = tid; i < ATC * JP; i += 256) {
        int t = i / JP, jp = i - t * JP;
        int j0 = 2 * jp, j1 = j0 + 1;
        size_t base = (size_t)(b * TDIM + t0 + t) * 64;
        float ga = g_g[base + j0];
        float gb = (j1 < KQ) ? g_g[base + j1] : 0.f;
        float ca = g_cs[base + j0];
        float cb = (j1 < KQ) ? g_cs[base + j1] : 0.f;
        ghh[t][jp] = __floats2half2_rn(ga, gb);
        csh[t][jp] = __floats2half2_rn(ca, cb);
    }
    __syncthreads();

    // 64*50 dot-products of length 49 (f16x2 tanh, f32 accumulate)
    for (int idx = tid; idx < ATC * 50; idx += 256) {
        const int t = idx / 50, k = idx - t * 50;
        const __half2* row = (k < KQ) ? &cvh[k][0] : &csh[t][0];
        const __half2* gr  = &ghh[t][0];
        float acc = 0.f;
        #pragma unroll 5
        for (int jp = 0; jp < JP; jp++) {
            __half2 s = __hadd2(row[jp], gr[jp]);
            unsigned th = h2tanh(*(unsigned*)&s);
            float2 tf = __half22float2(*(__half2*)&th);
            acc += tf.x * whsh[2 * jp] + tf.y * whsh[2 * jp + 1];
        }
        zsh[t][k] = acc;
    }
    __syncthreads();

    // per-t softmax (alpha over 49, beta from extended 50)
    if (tid < ATC) {
        const int t = tid;
        float mx = -1e30f;
        #pragma unroll 7
        for (int j = 0; j < KQ; j++) mx = fmaxf(mx, zsh[t][j]);
        float s = 0.f;
        #pragma unroll 7
        for (int j = 0; j < KQ; j++) {
            float e = __expf(zsh[t][j] - mx);
            zsh[t][j] = e; s += e;
        }
        inv_s[t] = 1.f / s;
        const float zx = zsh[t][49];
        const float M2 = fmaxf(mx, zx);
        const float denom = __expf(mx - M2) * s + __expf(zx - M2);
        g_be[b * TDIM + t0 + t] = __expf(zx - M2) / denom;
    }
    __syncthreads();

    // coalesced alpha writeback
    for (int i = tid; i < ATC * KQ; i += 256) {
        int t = i / KQ, j = i - t * KQ;
        g_al[(size_t)(b * TDIM + t0 + t) * 64 + j] = zsh[t][j] * inv_s[t];
    }
}

// ---------------- final: out = beta*s_t + (1-beta)*(alpha@V) + hiddens ------
__global__ void __launch_bounds__(256)
final_kernel(const float* __restrict__ V, const float* __restrict__ hiddens,
             float* __restrict__ out)
{
    const int b  = blockIdx.z;
    const int t0 = blockIdx.y * 16;
    const int h0 = blockIdx.x * 256;
    const int tid  = threadIdx.x;
    const int hthr = tid & 63;
    const int tthr = tid >> 6;

    __shared__ float al[16][52];
    __shared__ float be[16];

    for (int i = tid; i < 16 * KQ; i += 256) {
        int tt = i / KQ, k = i - tt * KQ;
        al[tt][k] = g_al[(size_t)(b * TDIM + t0 + tt) * 64 + k];
    }
    if (tid < 16) be[tid] = g_be[b * TDIM + t0 + tid];
    __syncthreads();

    const int h = h0 + hthr * 4;
    float4 acc[4];
    #pragma unroll
    for (int i = 0; i < 4; i++) acc[i] = make_float4(0.f, 0.f, 0.f, 0.f);

    const float* Vb = V + (size_t)b * KQ * HDIM + h;
    for (int k = 0; k < KQ; k++) {
        float4 v = *(const float4*)(Vb + (size_t)k * HDIM);
        #pragma unroll
        for (int i = 0; i < 4; i++) {
            float a = al[tthr * 4 + i][k];
            acc[i].x += a * v.x; acc[i].y += a * v.y;
            acc[i].z += a * v.z; acc[i].w += a * v.w;
        }
    }
    #pragma unroll
    for (int i = 0; i < 4; i++) {
        int t = t0 + tthr * 4 + i;
        size_t idx = ((size_t)(b * TDIM + t)) * HDIM + h;
        uint2 su = *(const uint2*)(g_st + idx);       // 4 fp16
        float2 s01 = __half22float2(*(__half2*)&su.x);
        float2 s23 = __half22float2(*(__half2*)&su.y);
        float4 hd = *(const float4*)(hiddens + idx);
        float bt = be[tthr * 4 + i];
        float om = 1.f - bt;
        float4 o;
        o.x = bt * s01.x + om * acc[i].x + hd.x;
        o.y = bt * s01.y + om * acc[i].y + hd.y;
        o.z = bt * s23.x + om * acc[i].z + hd.z;
        o.w = bt * s23.y + om * acc[i].w + hd.w;
        *(float4*)(out + idx) = o;
    }
}

// ---------------- launch ----------------
extern "C" void kernel_launch(void* const* d_in, const int* in_sizes, int n_in,
                              void* d_out, int out_size)
{
    const float* x       = (const float*)d_in[0];
    const float* hiddens = (const float*)d_in[1];
    const float* cells   = (const float*)d_in[2];
    const float* V       = (const float*)d_in[3];
    const float* Wx      = (const float*)d_in[4];
    // d_in[5] = Whh, unused: h_prev == 0 so its contribution is exactly zero.
    const float* Wv      = (const float*)d_in[6];
    const float* Wg      = (const float*)d_in[7];
    const float* Ws      = (const float*)d_in[8];
    const float* Wh      = (const float*)d_in[9];
    float* out = (float*)d_out;

    __nv_bfloat16 *p_xb, *p_wb; __half* p_wsh;
    float *p_g, *p_cs, *p_cv;
    cudaGetSymbolAddress((void**)&p_xb, g_xb);
    cudaGetSymbolAddress((void**)&p_wb, g_wb);
    cudaGetSymbolAddress((void**)&p_wsh, g_wsh);
    cudaGetSymbolAddress((void**)&p_g,  g_g);
    cudaGetSymbolAddress((void**)&p_cs, g_cs);
    cudaGetSymbolAddress((void**)&p_cv, g_cv);

    cudaFuncSetAttribute(gemm1_bf16_kernel,
                         cudaFuncAttributeMaxDynamicSharedMemorySize, G1_SMEM);
    cudaFuncSetAttribute(thin32_kernel,
                         cudaFuncAttributeMaxDynamicSharedMemorySize, T_SMEM);
    cudaFuncSetAttribute(thin16_kernel,
                         cudaFuncAttributeMaxDynamicSharedMemorySize, T_SMEM);

    // x, Wx -> bf16; Ws -> fp16 (padded)
    cvt_bf16_kernel<<<(MT_ROWS * HDIM / 4 + 255) / 256, 256>>>(x, p_xb,
                                                               MT_ROWS * HDIM / 4);
    cvt_bf16_kernel<<<(HDIM * HDIM / 4 + 255) / 256, 256>>>(Wx, p_wb,
                                                            HDIM * HDIM / 4);
    cvt_ws_kernel<<<256, 256>>>(Ws, p_wsh);

    // s_t = sigmoid(x @ Wx^T) * tanh(cells)  [32768 x 1024], bf16 HMMA
    gemm1_bf16_kernel<<<dim3(8, 256), 256, G1_SMEM>>>(cells);
    // g = hiddens @ Wg^T                     [32768 x 49]
    thin32_kernel<<<dim3(1, 256, 1), 256, T_SMEM>>>(hiddens, Wg, p_g,
                                                    MT_ROWS, KQ, 64, 0);
    // cs = s_t @ Ws^T                        [32768 x 49]  (fp16 HMMA)
    thin16_kernel<<<dim3(1, 256, 1), 256, T_SMEM>>>(p_cs);
    // cv = V @ Wv^T  (V as [3136, 1024]), K-split x4 into partial slices
    thin32_kernel<<<dim3(1, 25, 4), 256, T_SMEM>>>(V, Wv, p_cv,
                                                   3136, KQ, 64, CV_SLICE);
    // alpha / beta per (b, 64-t chunk)
    attn_logits_kernel<<<dim3(TDIM / ATC, BDIM), 256>>>(Wh);
    // out = beta*s_t + (1-beta)*(alpha@V) + hiddens
    final_kernel<<<dim3(4, 32, 64), 256>>>(V, hiddens, out);
}